// round 8
// baseline (speedup 1.0000x reference)
#include <cuda_runtime.h>
#include <math.h>

// ----------------------------------------------------------------------------
// FuncPitchEncoder R7: packed fp32x2 FFMA2 everywhere (GEMM, conv, VQ),
// cp.async W prefetch, row-pair interleaved conv smem.
// ----------------------------------------------------------------------------

#define BS      131072
#define LEN     128
#define NCH     10
#define CONVK   12
#define POOLN   29
#define FEATN   290
#define EMB     256
#define ZD      128
#define KC_     64
#define ROWS    128
#define NBLK    (BS / ROWS)
#define THR     512

#define KCH     29
#define CHF     (KCH * ZD)    // 3712 floats per chunk
#define NPHASE  5             // chunks per K-group (2 groups x 5)

// smem layout (floats)
#define FEATT_F   (FEATN * 132)              // 38280
#define REGA_F    14848                      // prs2 32*264=8448 | wbuf 4*3712 | Ct 128*68
#define OFF_REGA  FEATT_F
#define OFF_MISC  (FEATT_F + REGA_F)
#define PART_OFF  16896
#define SMEM_BYTES ((OFF_MISC + 356) * 4 + 192 * 4)   // 214704 B

typedef unsigned long long u64;

// ----------------------------- f32x2 helpers --------------------------------
__device__ __forceinline__ u64 pack2(float x, float y) {
    u64 d; asm("mov.b64 %0, {%1, %2};" : "=l"(d) : "f"(x), "f"(y)); return d;
}
__device__ __forceinline__ void unpack2(u64 v, float& lo, float& hi) {
    asm("mov.b64 {%0, %1}, %2;" : "=f"(lo), "=f"(hi) : "l"(v));
}
__device__ __forceinline__ u64 fma2(u64 a, u64 b, u64 c) {
    u64 d; asm("fma.rn.f32x2 %0, %1, %2, %3;" : "=l"(d) : "l"(a), "l"(b), "l"(c));
    return d;
}
__device__ __forceinline__ void cpasync16(const float* smem_dst, const void* g) {
    unsigned int sa = (unsigned int)__cvta_generic_to_shared(smem_dst);
    asm volatile("cp.async.cg.shared.global [%0], [%1], 16;" :: "r"(sa), "l"(g));
}
__device__ __forceinline__ void cpasync_commit() {
    asm volatile("cp.async.commit_group;");
}
__device__ __forceinline__ void cpasync_wait0() {
    asm volatile("cp.async.wait_group 0;");
}

// ----------------------------- device scratch -------------------------------
__device__ __align__(16) float g_W[FEATN * ZD];   // [k][j]
__device__ float g_bf[ZD];
__device__ float g_cnorm[KC_];
__device__ float g_csum;
__device__ int   g_counts[KC_];
__device__ int   g_mask_u8;

// ----------------------------- setup kernel ---------------------------------
__global__ void setup_kernel(const float* __restrict__ fc_b,
                             const float* __restrict__ mu_w,
                             const float* __restrict__ mu_b,
                             const float* __restrict__ cb)
{
    int t = threadIdx.x;
    if (t == 0) { g_csum = 0.f; g_mask_u8 = 0; }
    if (t < KC_) g_counts[t] = 0;
    if (t < ZD) {
        float a = mu_b[t];
        for (int e = 0; e < EMB; e++) a = fmaf(mu_w[t * EMB + e], fc_b[e], a);
        g_bf[t] = a;
    }
    if (t >= 128 && t < 128 + KC_) {
        int k = t - 128;
        float a = 0.f;
        for (int z = 0; z < ZD; z++) { float c = cb[k * ZD + z]; a = fmaf(c, c, a); }
        g_cnorm[k] = a;
    }
}

// ------------------------- mask dtype detection -----------------------------
__global__ void detect_kernel(const unsigned char* __restrict__ m, int n)
{
    int i = blockIdx.x * blockDim.x + threadIdx.x;
    int f = 0;
    if (i < n && (i & 3)) f = (m[i] != 0);
    if (__any_sync(0xffffffffu, f)) {
        if ((threadIdx.x & 31) == 0) atomicOr(&g_mask_u8, 1);
    }
}

// ------------------------- fused-W precompute -------------------------------
__global__ void wfuse_kernel(const float* __restrict__ fc_w,
                             const float* __restrict__ mu_w)
{
    __shared__ float colw[EMB * 4];
    int t = threadIdx.x;
    int k0 = blockIdx.x * 4;
    for (int i = t; i < EMB * 4; i += 128) {
        int e = i >> 2, kk = i & 3, k = k0 + kk;
        colw[i] = (k < FEATN) ? fc_w[e * FEATN + k] : 0.f;
    }
    __syncthreads();
    float a0 = 0.f, a1 = 0.f, a2 = 0.f, a3 = 0.f;
    const float* mr = mu_w + t * EMB;
    #pragma unroll 4
    for (int e = 0; e < EMB; e++) {
        float m = mr[e];
        a0 = fmaf(m, colw[e * 4 + 0], a0);
        a1 = fmaf(m, colw[e * 4 + 1], a1);
        a2 = fmaf(m, colw[e * 4 + 2], a2);
        a3 = fmaf(m, colw[e * 4 + 3], a3);
    }
    if (k0 + 0 < FEATN) g_W[(k0 + 0) * ZD + t] = a0;
    if (k0 + 1 < FEATN) g_W[(k0 + 1) * ZD + t] = a1;
    if (k0 + 2 < FEATN) g_W[(k0 + 2) * ZD + t] = a2;
    if (k0 + 3 < FEATN) g_W[(k0 + 3) * ZD + t] = a3;
}

// --------------------------- conv worker (row pair) --------------------------
// One (row-pair, channel) item: packed conv k=12 + relu + maxpool4 for TWO rows
// simultaneously via fma.rn.f32x2. prs2 interleaves the two rows so
// ld.shared.b64 yields a ready packed operand.
__device__ __noinline__ void conv_pair(const float* __restrict__ prs2,
                                       float* __restrict__ featT,
                                       const float* __restrict__ s_convw,
                                       const float* __restrict__ s_convb,
                                       int item, int rowbase)
{
    int rp = item / NCH;
    int ch = item - rp * NCH;
    int rloc = rowbase + rp * 2;
    u64 w2[CONVK];
    #pragma unroll
    for (int i = 0; i < CONVK; i++) {
        float w = s_convw[ch * CONVK + i];
        w2[i] = pack2(w, w);
    }
    float bb = s_convb[ch];
    u64 b2 = pack2(bb, bb);
    const u64* prow = (const u64*)&prs2[rp * 264];
    float* fp = &featT[ch * POOLN * 132 + rloc];
    u64 x[15];
    #pragma unroll
    for (int i = 0; i < 15; i++) x[i] = prow[i];
    #pragma unroll
    for (int p = 0; p < POOLN; p++) {
        float mA = 0.f, mB = 0.f;       // relu >= 0
        #pragma unroll
        for (int j = 0; j < 4; j++) {
            u64 acc = b2;
            #pragma unroll
            for (int tt = 0; tt < CONVK; tt++)
                acc = fma2(x[j + tt], w2[tt], acc);
            float lo, hi; unpack2(acc, lo, hi);
            mA = fmaxf(mA, lo);
            mB = fmaxf(mB, hi);
        }
        *(u64*)(fp + p * 132) = pack2(mA, mB);
        if (p < POOLN - 1) {
            #pragma unroll
            for (int i = 0; i < 11; i++) x[i] = x[i + 4];
            #pragma unroll
            for (int i = 0; i < 4; i++) x[11 + i] = prow[4 * p + 15 + i];
        }
    }
}

// ------------------------------ main kernel ---------------------------------
__global__ __launch_bounds__(THR, 1)
void main_kernel(const float* __restrict__ pr,
                 const void*  __restrict__ mask,
                 const float* __restrict__ conv_w,
                 const float* __restrict__ conv_b,
                 const float* __restrict__ cb,
                 float* __restrict__ out)
{
    extern __shared__ float sm[];
    float* featT    = sm;                       // [290][132]; later mu_t + partials
    float* regA     = sm + OFF_REGA;            // prs2 | wbuf x4 | Ct
    float* s_convw  = sm + OFF_MISC;            // 120
    float* s_convb  = s_convw + 120;            // 12
    float* s_bf     = s_convb + 12;             // 128
    float* s_cnorm  = s_bf + 128;               // 64
    float* s_red    = s_cnorm + 64;             // 32
    int*   s_idx    = (int*)(s_red + 32);       // 128
    int*   s_counts = s_idx + 128;              // 64

    const int t   = threadIdx.x;
    const int blk = blockIdx.x;

    // ---- misc loads ----
    for (int i = t; i < 120; i += THR) s_convw[i] = conv_w[i];
    if (t < NCH)  s_convb[t] = conv_b[t];
    if (t < ZD)   s_bf[t]    = g_bf[t];
    if (t < KC_) { s_cnorm[t] = g_cnorm[t]; s_counts[t] = 0; }

    // =============== Phase 1: conv + relu + maxpool -> featT ===============
    // prs2: 32 row-pairs x 128 cols x 2 (interleaved rows), stride 264
    float* prs2 = regA;
    for (int sub = 0; sub < 2; sub++) {
        int row0 = blk * ROWS + sub * 64;
        __syncthreads();                        // prs2 reuse / misc ready
        const float4* src4 = (const float4*)(pr + (size_t)row0 * LEN);
        for (int i = t; i < 32 * 32; i += THR) {   // rp, c4
            int rp = i >> 5, c4 = i & 31;
            float4 a = src4[(2 * rp)     * 32 + c4];
            float4 b = src4[(2 * rp + 1) * 32 + c4];
            u64* dst = (u64*)&prs2[rp * 264 + c4 * 8];
            dst[0] = pack2(a.x, b.x);
            dst[1] = pack2(a.y, b.y);
            dst[2] = pack2(a.z, b.z);
            dst[3] = pack2(a.w, b.w);
        }
        __syncthreads();
        if (t < 320) conv_pair(prs2, featT, s_convw, s_convb, t, sub * 64);
    }
    __syncthreads();                            // featT complete, prs2 dead

    // =============== Phase 2: mu = featT^T @ W + b, K-split x2, FFMA2 ======
    const int g  = t >> 8;                      // 0 / 1
    const int tg = t & 255;
    const int r0 = (tg >> 4) * 8;
    const int j0 = (tg & 15) * 8;
    u64 acc[32];                                // 8 rows x 4 col-pairs
    #pragma unroll
    for (int i = 0; i < 32; i++) acc[i] = 0ULL;

    const float4* gW4 = (const float4*)g_W;

    // prologue: cp.async chunk pair 0 into buffer 0
    #pragma unroll
    for (int u = 0; u < 4; u++) {
        int i = t + u * THR;
        if (i < 1856) {
            int grp = i / 928, j = i - grp * 928;
            cpasync16(&regA[grp * CHF + j * 4],
                      &gW4[(grp * NPHASE + 0) * 928 + j]);
        }
    }
    cpasync_commit();
    cpasync_wait0();
    __syncthreads();

    for (int p = 0; p < NPHASE; p++) {
        if (p < NPHASE - 1) {
            float* nb = regA + (((p + 1) & 1) * 2) * CHF;
            #pragma unroll
            for (int u = 0; u < 4; u++) {
                int i = t + u * THR;
                if (i < 1856) {
                    int grp = i / 928, j = i - grp * 928;
                    cpasync16(&nb[grp * CHF + j * 4],
                              &gW4[(grp * NPHASE + p + 1) * 928 + j]);
                }
            }
            cpasync_commit();
        }
        const float* wb = regA + ((p & 1) * 2 + g) * CHF;
        const int krow0 = (g * NPHASE + p) * KCH;
        #pragma unroll 4
        for (int kc = 0; kc < KCH; kc++) {
            const float* fa = &featT[(krow0 + kc) * 132 + r0];
            float4 a0 = *(const float4*)(fa);
            float4 a1 = *(const float4*)(fa + 4);
            const ulonglong2* fb = (const ulonglong2*)&wb[kc * ZD + j0];
            ulonglong2 b01 = fb[0];
            ulonglong2 b23 = fb[1];
            u64 bp[4] = {b01.x, b01.y, b23.x, b23.y};
            float av[8] = {a0.x, a0.y, a0.z, a0.w, a1.x, a1.y, a1.z, a1.w};
            #pragma unroll
            for (int ii = 0; ii < 8; ii++) {
                u64 ad = pack2(av[ii], av[ii]);
                #pragma unroll
                for (int jp = 0; jp < 4; jp++)
                    acc[ii * 4 + jp] = fma2(ad, bp[jp], acc[ii * 4 + jp]);
            }
        }
        if (p < NPHASE - 1) cpasync_wait0();
        __syncthreads();
    }

    // unpack accumulators to scalar layout acc_s[ii*8+jj]
    float acc_s[64];
    #pragma unroll
    for (int ii = 0; ii < 8; ii++)
        #pragma unroll
        for (int jp = 0; jp < 4; jp++)
            unpack2(acc[ii * 4 + jp], acc_s[ii * 8 + 2 * jp], acc_s[ii * 8 + 2 * jp + 1]);

    // ---- merge K-split partials; write mu transposed; load Ct ----
    float* part = featT + PART_OFF;             // 256*64 floats
    float* mu_t = featT;                        // [128][132]
    float* Ct   = regA;                         // [128][68]
    if (g == 1) {
        float4* pp = (float4*)(part + tg * 64);
        #pragma unroll
        for (int i = 0; i < 16; i++)
            pp[i] = make_float4(acc_s[4*i], acc_s[4*i+1], acc_s[4*i+2], acc_s[4*i+3]);
    }
    __syncthreads();
    if (g == 0) {
        const float* pp = part + tg * 64;
        #pragma unroll
        for (int i = 0; i < 64; i++) acc_s[i] += pp[i];
        #pragma unroll
        for (int jj = 0; jj < 8; jj++) {
            float b = s_bf[j0 + jj];
            float* mrow = &mu_t[(j0 + jj) * 132 + r0];
            *(float4*)(mrow)     = make_float4(acc_s[0*8+jj]+b, acc_s[1*8+jj]+b,
                                               acc_s[2*8+jj]+b, acc_s[3*8+jj]+b);
            *(float4*)(mrow + 4) = make_float4(acc_s[4*8+jj]+b, acc_s[5*8+jj]+b,
                                               acc_s[6*8+jj]+b, acc_s[7*8+jj]+b);
        }
    } else {
        for (int i = tg; i < KC_ * ZD; i += 256) {
            int c = i >> 7, z = i & 127;
            Ct[z * 68 + c] = cb[i];
        }
    }
    __syncthreads();

    // =============== Phase 3: scores = mu @ C^T + argmin (FFMA2) ===========
    {
        const int ty3 = t >> 4, tx3 = t & 15;
        const int rr0 = ty3 * 4, c0 = tx3 * 4;   // 4 rows x 4 codes (2 pairs)
        u64 sacc[8];
        #pragma unroll
        for (int i = 0; i < 8; i++) sacc[i] = 0ULL;
        #pragma unroll 4
        for (int z = 0; z < ZD; z++) {
            float4 m = *(const float4*)&mu_t[z * 132 + rr0];
            ulonglong2 cc = *(const ulonglong2*)&Ct[z * 68 + c0];
            u64 cp2[2] = {cc.x, cc.y};
            float mv[4] = {m.x, m.y, m.z, m.w};
            #pragma unroll
            for (int ii = 0; ii < 4; ii++) {
                u64 md = pack2(mv[ii], mv[ii]);
                #pragma unroll
                for (int jp = 0; jp < 2; jp++)
                    sacc[ii * 2 + jp] = fma2(md, cp2[jp], sacc[ii * 2 + jp]);
            }
        }
        #pragma unroll
        for (int ii = 0; ii < 4; ii++) {
            float s[4];
            unpack2(sacc[ii * 2 + 0], s[0], s[1]);
            unpack2(sacc[ii * 2 + 1], s[2], s[3]);
            float bv = 3.4e38f; int bi = 0;
            #pragma unroll
            for (int jj = 0; jj < 4; jj++) {
                float kv = s_cnorm[c0 + jj] - 2.f * s[jj];
                if (kv < bv) { bv = kv; bi = c0 + jj; }
            }
            #pragma unroll
            for (int o = 1; o < 16; o <<= 1) {
                float ov = __shfl_xor_sync(0xffffffffu, bv, o);
                int   oi = __shfl_xor_sync(0xffffffffu, bi, o);
                if (ov < bv || (ov == bv && oi < bi)) { bv = ov; bi = oi; }
            }
            if (tx3 == 0) s_idx[rr0 + ii] = bi;
        }
    }
    __syncthreads();

    // =============== Phase 4: commitment, counts, z output =================
    const int flag_u8 = g_mask_u8;
    float cs = 0.f;
    int validrow = 0;
    if (t < ROWS) {
        int rg = blk * ROWS + t;
        validrow = flag_u8 ? (((const unsigned char*)mask)[rg] == 0)
                           : (((const int*)mask)[rg] == 0);
        int myidx = s_idx[t];
        #pragma unroll 4
        for (int z = 0; z < ZD; z++) {
            float d = Ct[z * 68 + myidx] - mu_t[z * 132 + t];
            cs = fmaf(d, d, cs);
        }
        if (validrow) atomicAdd(&s_counts[myidx], 1);
    }
    float v = (t < ROWS && validrow) ? cs : 0.f;
    #pragma unroll
    for (int o = 16; o > 0; o >>= 1) v += __shfl_down_sync(0xffffffffu, v, o);
    if ((t & 31) == 0) s_red[t >> 5] = v;
    __syncthreads();
    if (t == 0) {
        float tot = 0.f;
        for (int w = 0; w < 16; w++) tot += s_red[w];
        atomicAdd(&g_csum, tot);
    }
    if (t < KC_ && s_counts[t]) atomicAdd(&g_counts[t], s_counts[t]);

    // z = codebook[idx], vectorized
    float4* out4 = (float4*)(out + (size_t)blk * (ROWS * ZD));
    const float4* cb4 = (const float4*)cb;
    for (int i = t; i < ROWS * ZD / 4; i += THR) {
        int r = i >> 5, z4 = i & 31;
        out4[i] = cb4[s_idx[r] * 32 + z4];
    }
}

// ------------------------------ finalize ------------------------------------
__global__ void final_kernel(float* __restrict__ out)
{
    if (threadIdx.x == 0) {
        int nvi = 0;
        for (int k = 0; k < KC_; k++) nvi += g_counts[k];
        float nv = fmaxf((float)nvi, 1.f);
        float H = 0.f;
        for (int k = 0; k < KC_; k++) {
            float p = (float)g_counts[k] / nv;
            H += p * logf(p + 1e-10f);
        }
        out[(long)BS * ZD]     = 0.25f * g_csum / (nv * (float)ZD);
        out[(long)BS * ZD + 1] = expf(-H);
    }
}

// ------------------------------- launcher -----------------------------------
extern "C" void kernel_launch(void* const* d_in, const int* in_sizes, int n_in,
                              void* d_out, int out_size)
{
    const float* pr      = (const float*)d_in[0];
    const void*  mask    = d_in[1];
    const float* conv_w  = (const float*)d_in[2];
    const float* conv_b  = (const float*)d_in[3];
    const float* fc_w    = (const float*)d_in[4];
    const float* fc_b    = (const float*)d_in[5];
    const float* mu_w    = (const float*)d_in[6];
    const float* mu_b    = (const float*)d_in[7];
    const float* cb      = (const float*)d_in[8];
    float* out = (float*)d_out;

    cudaFuncSetAttribute(main_kernel,
                         cudaFuncAttributeMaxDynamicSharedMemorySize, SMEM_BYTES);

    setup_kernel<<<1, 256>>>(fc_b, mu_w, mu_b, cb);
    detect_kernel<<<(BS + 255) / 256, 256>>>((const unsigned char*)mask, BS);
    wfuse_kernel<<<(FEATN + 3) / 4, 128>>>(fc_w, mu_w);
    main_kernel<<<NBLK, THR, SMEM_BYTES>>>(pr, mask, conv_w, conv_b, cb, out);
    final_kernel<<<1, 32>>>(out);
}

// round 10
// speedup vs baseline: 1.0321x; 1.0321x over previous
#include <cuda_runtime.h>
#include <cuda_bf16.h>
#include <math.h>
#include <stdint.h>

// ----------------------------------------------------------------------------
// FuncPitchEncoder R9: scalar conv (R6) + baseline mma.sync bf16 3-split GEMM
//   mu = feat @ W via 6 HMMA combos (a_i * b_j, i+j<=2) -> fp32-class accuracy
//   VQ / cmt / perplexity scalar (R6).
// ----------------------------------------------------------------------------

#define BS      131072
#define LEN     128
#define NCH     10
#define CONVK   12
#define POOLN   29
#define FEATN   290
#define EMB     256
#define ZD      128
#define KC_     64
#define ROWS    128
#define NBLK    (BS / ROWS)
#define THR     512

#define KPAD    320                      // K padded to 20 k16-tiles
#define NKT     20                       // total k16 tiles
#define NCHUNK  5                        // 5 chunks x 64 K each

// smem float offsets
#define FEATT_F   38280                  // featT [290][132]; later mu_t [128][132]
#define OFF_SCR   FEATT_F                // scr right after featT
#define SCR_U32   12288                  // max(prs 8448f, afrag 12288u32, Ct 8704f)
#define OFF_MISC  (FEATT_F + SCR_U32)    // 50568
#define SMEM_F    (OFF_MISC + 356 + 192)
#define SMEM_BYTES (SMEM_F * 4)          // 204464 B

// ----------------------------- helpers --------------------------------------
__device__ __forceinline__ unsigned short bfbits(float v) {
    return __bfloat16_as_ushort(__float2bfloat16(v));
}

#define MMA16816(d, a, b) \
    asm volatile("mma.sync.aligned.m16n8k16.row.col.f32.bf16.bf16.f32 " \
        "{%0,%1,%2,%3}, {%4,%5,%6,%7}, {%8,%9}, {%0,%1,%2,%3};" \
        : "+f"((d)[0]), "+f"((d)[1]), "+f"((d)[2]), "+f"((d)[3]) \
        : "r"((a)[0]), "r"((a)[1]), "r"((a)[2]), "r"((a)[3]), \
          "r"((b)[0]), "r"((b)[1]))

// ----------------------------- device scratch -------------------------------
// B fragments: [ktile 20][plane 3][ntile 16][lane 32][reg 2] uint32
__device__ __align__(16) uint32_t g_Bfrag[NKT * 3 * 16 * 32 * 2];
__device__ float g_bf[ZD];
__device__ float g_cnorm[KC_];
__device__ float g_csum;
__device__ int   g_counts[KC_];
__device__ int   g_mask_u8;

// ----------------------------- setup kernel ---------------------------------
__global__ void setup_kernel(const float* __restrict__ fc_b,
                             const float* __restrict__ mu_w,
                             const float* __restrict__ mu_b,
                             const float* __restrict__ cb)
{
    int t = threadIdx.x;
    if (t == 0) { g_csum = 0.f; g_mask_u8 = 0; }
    if (t < KC_) g_counts[t] = 0;
    if (t < ZD) {
        float a = mu_b[t];
        for (int e = 0; e < EMB; e++) a = fmaf(mu_w[t * EMB + e], fc_b[e], a);
        g_bf[t] = a;
    }
    if (t >= 128 && t < 128 + KC_) {
        int k = t - 128;
        float a = 0.f;
        for (int z = 0; z < ZD; z++) { float c = cb[k * ZD + z]; a = fmaf(c, c, a); }
        g_cnorm[k] = a;
    }
}

// ------------------------- mask dtype detection -----------------------------
__global__ void detect_kernel(const unsigned char* __restrict__ m, int n)
{
    int i = blockIdx.x * blockDim.x + threadIdx.x;
    int f = 0;
    if (i < n && (i & 3)) f = (m[i] != 0);
    if (__any_sync(0xffffffffu, f)) {
        if ((threadIdx.x & 31) == 0) atomicOr(&g_mask_u8, 1);
    }
}

// ------------------- fused-W precompute -> bf16 frag planes ------------------
// W[k][j] = sum_e mu_w[j][e] fc_w[e][k]; 3-term bf16 split stored directly in
// mma.m16n8k16 B-fragment order (logical B[k][n], n=j).
__global__ void wfuse_kernel(const float* __restrict__ fc_w,
                             const float* __restrict__ mu_w)
{
    __shared__ float colw[EMB * 4];
    int t = threadIdx.x;                 // j = 0..127
    int k0 = blockIdx.x * 4;
    for (int i = t; i < EMB * 4; i += 128) {
        int e = i >> 2, kk = i & 3, k = k0 + kk;
        colw[i] = (k < FEATN) ? fc_w[e * FEATN + k] : 0.f;
    }
    __syncthreads();
    float a[4] = {0.f, 0.f, 0.f, 0.f};
    const float* mr = mu_w + t * EMB;
    #pragma unroll 4
    for (int e = 0; e < EMB; e++) {
        float m = mr[e];
        a[0] = fmaf(m, colw[e * 4 + 0], a[0]);
        a[1] = fmaf(m, colw[e * 4 + 1], a[1]);
        a[2] = fmaf(m, colw[e * 4 + 2], a[2]);
        a[3] = fmaf(m, colw[e * 4 + 3], a[3]);
    }
    unsigned short* B16 = (unsigned short*)g_Bfrag;
    #pragma unroll
    for (int kk = 0; kk < 4; kk++) {
        int k = k0 + kk;                 // 0..319
        float wv = a[kk];
        float p0f = __bfloat162float(__float2bfloat16(wv));
        float r1  = wv - p0f;
        float p1f = __bfloat162float(__float2bfloat16(r1));
        float r2  = r1 - p1f;
        unsigned short h[3] = { bfbits(wv), bfbits(r1), bfbits(r2) };
        int gkt = k >> 4, klt = k & 15;
        int regb = klt >> 3, half = klt & 1;
        int tB = ((t & 7) << 2) + ((klt & 7) >> 1);
        int nt = t >> 3;
        #pragma unroll
        for (int p = 0; p < 3; p++) {
            int idx16 = (((((gkt * 3 + p) * 16 + nt) * 32 + tB) * 2 + regb) << 1) + half;
            B16[idx16] = h[p];
        }
    }
}

// --------------------------- conv worker (scalar, R6) ------------------------
__device__ __noinline__ void conv_item(const float* __restrict__ prs,
                                       float* __restrict__ featT,
                                       const float* __restrict__ s_convw,
                                       const float* __restrict__ s_convb,
                                       int item, int rowbase)
{
    int rl = item / NCH;
    int ch = item - rl * NCH;
    int rloc = rowbase + rl;
    float wr[CONVK];
    #pragma unroll
    for (int i = 0; i < CONVK; i++) wr[i] = s_convw[ch * CONVK + i];
    float bb = s_convb[ch];
    const float* prow = &prs[rl * 132];
    float* fp = &featT[ch * POOLN * 132 + rloc];
    float x[15];
    #pragma unroll
    for (int i = 0; i < 15; i++) x[i] = prow[i];
    #pragma unroll
    for (int p = 0; p < POOLN; p++) {
        float m = 0.f;                   // relu >= 0
        #pragma unroll
        for (int j = 0; j < 4; j++) {
            float acc = bb;
            #pragma unroll
            for (int tt = 0; tt < CONVK; tt++)
                acc = fmaf(x[j + tt], wr[tt], acc);
            m = fmaxf(m, acc);
        }
        fp[p * 132] = m;
        if (p < POOLN - 1) {
            #pragma unroll
            for (int i = 0; i < 11; i++) x[i] = x[i + 4];
            #pragma unroll
            for (int i = 0; i < 4; i++) x[11 + i] = prow[4 * p + 15 + i];
        }
    }
}

// ------------------------------ main kernel ---------------------------------
__global__ __launch_bounds__(THR, 1)
void main_kernel(const float* __restrict__ pr,
                 const void*  __restrict__ mask,
                 const float* __restrict__ conv_w,
                 const float* __restrict__ conv_b,
                 const float* __restrict__ cb,
                 float* __restrict__ out)
{
    extern __shared__ float sm[];
    float* featT    = sm;                       // [290][132]; later mu_t [128][132]
    float* scr      = sm + OFF_SCR;             // prs | afrag | Ct
    float* s_convw  = sm + OFF_MISC;            // 120
    float* s_convb  = s_convw + 120;            // 12
    float* s_bf     = s_convb + 12;             // 128
    float* s_cnorm  = s_bf + 128;               // 64
    float* s_red    = s_cnorm + 64;             // 32
    int*   s_idx    = (int*)(sm + OFF_MISC + 356);    // 128
    int*   s_counts = s_idx + 128;                     // 64

    const int t    = threadIdx.x;
    const int blk  = blockIdx.x;
    const int lane = t & 31;
    const int w    = t >> 5;
    const int mi   = w >> 2;                    // 0..3: rows 32*mi
    const int ni   = w & 3;                     // 0..3: cols 32*ni

    // ---- misc loads ----
    for (int i = t; i < 120; i += THR) s_convw[i] = conv_w[i];
    if (t < NCH)  s_convb[t] = conv_b[t];
    if (t < ZD)   s_bf[t]    = g_bf[t];
    if (t < KC_) { s_cnorm[t] = g_cnorm[t]; s_counts[t] = 0; }

    // =============== Phase 1: conv + relu + maxpool -> featT ===============
    float* prs = scr;                           // [64][132]
    for (int sub = 0; sub < 2; sub++) {
        int row0 = blk * ROWS + sub * 64;
        __syncthreads();                        // prs reuse / misc ready
        const float4* src = (const float4*)(pr + (size_t)row0 * LEN);
        for (int i = t; i < 64 * 32; i += THR) {
            int rr = i >> 5, c4 = i & 31;
            *(float4*)&prs[rr * 132 + c4 * 4] = src[i];
        }
        __syncthreads();
        conv_item(prs, featT, s_convw, s_convb, t, sub * 64);
        if (t < 128) conv_item(prs, featT, s_convw, s_convb, t + THR, sub * 64);
    }
    __syncthreads();                            // featT complete, prs dead

    // =============== Phase 2: mu = feat @ W via 6 bf16 HMMA combos =========
    uint32_t* afrag = (uint32_t*)scr;           // [4 kt][3 p][8 mtile][32 lane][4 reg]
    float d[2][4][4];
    #pragma unroll
    for (int i = 0; i < 2; i++)
        #pragma unroll
        for (int j = 0; j < 4; j++)
            #pragma unroll
            for (int q = 0; q < 4; q++) d[i][j][q] = 0.f;

    for (int c = 0; c < NCHUNK; c++) {
        const int k0c = c * 64;
        // ---- convert featT chunk -> 3 bf16 planes in A-fragment order ----
        #pragma unroll
        for (int s = 0; s < 8; s++) {
            int idx = s * THR + t;              // 0..4095
            int r   = idx & 127;
            int kle = (idx >> 7) * 2;           // even k within chunk
            int k   = k0c + kle;
            float v0 = (k     < FEATN) ? featT[k * 132 + r]       : 0.f;
            float v1 = (k + 1 < FEATN) ? featT[(k + 1) * 132 + r] : 0.f;
            float p00 = __bfloat162float(__float2bfloat16(v0));
            float r10 = v0 - p00;
            float p10 = __bfloat162float(__float2bfloat16(r10));
            float r20 = r10 - p10;
            float p01 = __bfloat162float(__float2bfloat16(v1));
            float r11 = v1 - p01;
            float p11 = __bfloat162float(__float2bfloat16(r11));
            float r21 = r11 - p11;
            unsigned short lo[3] = { bfbits(v0), bfbits(r10), bfbits(r20) };
            unsigned short hi[3] = { bfbits(v1), bfbits(r11), bfbits(r21) };
            int ktl = kle >> 4, klt = kle & 15;
            int reg = ((r & 15) >> 3) + ((klt >> 3) << 1);
            int tA  = ((r & 7) << 2) + ((klt & 7) >> 1);
            int mt  = r >> 4;
            #pragma unroll
            for (int p = 0; p < 3; p++)
                afrag[(((ktl * 3 + p) * 8 + mt) << 7) + (tA << 2) + reg]
                    = (uint32_t)lo[p] | ((uint32_t)hi[p] << 16);
        }
        __syncthreads();

        // ---- 4 k16 steps: load frags + 48 MMAs each ----
        #pragma unroll
        for (int kt = 0; kt < 4; kt++) {
            const int gkt = c * 4 + kt;
            uint32_t b[3][4][2];
            #pragma unroll
            for (int p = 0; p < 3; p++)
                #pragma unroll
                for (int q = 0; q < 4; q++) {
                    const uint2 bb = *(const uint2*)&g_Bfrag[
                        ((((gkt * 3 + p) * 16 + (ni * 4 + q)) * 32 + lane) << 1)];
                    b[p][q][0] = bb.x; b[p][q][1] = bb.y;
                }
            uint32_t a[3][2][4];
            #pragma unroll
            for (int p = 0; p < 3; p++)
                #pragma unroll
                for (int s2 = 0; s2 < 2; s2++) {
                    const uint4 aa = *(const uint4*)&afrag[
                        (((kt * 3 + p) * 8 + (mi * 2 + s2)) << 7) + (lane << 2)];
                    a[p][s2][0] = aa.x; a[p][s2][1] = aa.y;
                    a[p][s2][2] = aa.z; a[p][s2][3] = aa.w;
                }
            #pragma unroll
            for (int s2 = 0; s2 < 2; s2++)
                #pragma unroll
                for (int q = 0; q < 4; q++) {
                    MMA16816(d[s2][q], a[0][s2], b[0][q]);
                    MMA16816(d[s2][q], a[0][s2], b[1][q]);
                    MMA16816(d[s2][q], a[1][s2], b[0][q]);
                    MMA16816(d[s2][q], a[1][s2], b[1][q]);
                    MMA16816(d[s2][q], a[2][s2], b[0][q]);
                    MMA16816(d[s2][q], a[0][s2], b[2][q]);
                }
        }
        __syncthreads();                        // afrag reuse for next chunk
    }

    // =============== Epilogue: D frags -> mu_t (+bias); load Ct ============
    float* mu_t = featT;                        // [128][132]
    float* Ct   = scr;                          // [128][68]
    {
        const int rbase = mi * 32 + (lane >> 2);
        const int nbase = ni * 32 + (lane & 3) * 2;
        #pragma unroll
        for (int s2 = 0; s2 < 2; s2++)
            #pragma unroll
            for (int q = 0; q < 4; q++) {
                int r0 = rbase + s2 * 16;
                int n0 = nbase + q * 8;
                float b0 = s_bf[n0], b1 = s_bf[n0 + 1];
                mu_t[n0 * 132 + r0]           = d[s2][q][0] + b0;
                mu_t[(n0 + 1) * 132 + r0]     = d[s2][q][1] + b1;
                mu_t[n0 * 132 + r0 + 8]       = d[s2][q][2] + b0;
                mu_t[(n0 + 1) * 132 + r0 + 8] = d[s2][q][3] + b1;
            }
    }
    __syncthreads();                            // mu_t done before Ct fills scr
    for (int i = t; i < KC_ * ZD; i += THR) {
        int cc = i >> 7, z = i & 127;           // Ct[z][c] = cb[c][z]
        Ct[z * 68 + cc] = cb[i];
    }
    __syncthreads();

    // =============== Phase 3: scores = mu @ C^T + argmin (scalar) ==========
    {
        const int ty3 = t >> 4, tx3 = t & 15;
        const int rr0 = ty3 * 4, c0 = tx3 * 4;
        float sacc[16];
        #pragma unroll
        for (int i = 0; i < 16; i++) sacc[i] = 0.f;
        #pragma unroll 4
        for (int z = 0; z < ZD; z++) {
            float4 m = *(const float4*)&mu_t[z * 132 + rr0];
            float4 cv4 = *(const float4*)&Ct[z * 68 + c0];
            float mv[4] = {m.x, m.y, m.z, m.w};
            float cv[4] = {cv4.x, cv4.y, cv4.z, cv4.w};
            #pragma unroll
            for (int ii = 0; ii < 4; ii++)
                #pragma unroll
                for (int jj = 0; jj < 4; jj++)
                    sacc[ii * 4 + jj] = fmaf(mv[ii], cv[jj], sacc[ii * 4 + jj]);
        }
        #pragma unroll
        for (int ii = 0; ii < 4; ii++) {
            float bv = 3.4e38f; int bi = 0;
            #pragma unroll
            for (int jj = 0; jj < 4; jj++) {
                float kv = s_cnorm[c0 + jj] - 2.f * sacc[ii * 4 + jj];
                if (kv < bv) { bv = kv; bi = c0 + jj; }
            }
            #pragma unroll
            for (int o = 1; o < 16; o <<= 1) {
                float ov = __shfl_xor_sync(0xffffffffu, bv, o);
                int   oi = __shfl_xor_sync(0xffffffffu, bi, o);
                if (ov < bv || (ov == bv && oi < bi)) { bv = ov; bi = oi; }
            }
            if (tx3 == 0) s_idx[rr0 + ii] = bi;
        }
    }
    __syncthreads();

    // =============== Phase 4: commitment, counts, z output =================
    const int flag_u8 = g_mask_u8;
    float cs = 0.f;
    int validrow = 0;
    if (t < ROWS) {
        int rg = blk * ROWS + t;
        validrow = flag_u8 ? (((const unsigned char*)mask)[rg] == 0)
                           : (((const int*)mask)[rg] == 0);
        int myidx = s_idx[t];
        #pragma unroll 4
        for (int z = 0; z < ZD; z++) {
            float dd = Ct[z * 68 + myidx] - mu_t[z * 132 + t];
            cs = fmaf(dd, dd, cs);
        }
        if (validrow) atomicAdd(&s_counts[myidx], 1);
    }
    float v = (t < ROWS && validrow) ? cs : 0.f;
    #pragma unroll
    for (int o = 16; o > 0; o >>= 1) v += __shfl_down_sync(0xffffffffu, v, o);
    if ((t & 31) == 0) s_red[t >> 5] = v;
    __syncthreads();
    if (t == 0) {
        float tot = 0.f;
        for (int ww = 0; ww < 16; ww++) tot += s_red[ww];
        atomicAdd(&g_csum, tot);
    }
    if (t < KC_ && s_counts[t]) atomicAdd(&g_counts[t], s_counts[t]);

    // z = codebook[idx], vectorized
    float4* out4 = (float4*)(out + (size_t)blk * (ROWS * ZD));
    const float4* cb4 = (const float4*)cb;
    for (int i = t; i < ROWS * ZD / 4; i += THR) {
        int r = i >> 5, z4 = i & 31;
        out4[i] = cb4[s_idx[r] * 32 + z4];
    }
}

// ------------------------------ finalize ------------------------------------
__global__ void final_kernel(float* __restrict__ out)
{
    if (threadIdx.x == 0) {
        int nvi = 0;
        for (int k = 0; k < KC_; k++) nvi += g_counts[k];
        float nv = fmaxf((float)nvi, 1.f);
        float H = 0.f;
        for (int k = 0; k < KC_; k++) {
            float p = (float)g_counts[k] / nv;
            H += p * logf(p + 1e-10f);
        }
        out[(long)BS * ZD]     = 0.25f * g_csum / (nv * (float)ZD);
        out[(long)BS * ZD + 1] = expf(-H);
    }
}

// ------------------------------- launcher -----------------------------------
extern "C" void kernel_launch(void* const* d_in, const int* in_sizes, int n_in,
                              void* d_out, int out_size)
{
    const float* pr      = (const float*)d_in[0];
    const void*  mask    = d_in[1];
    const float* conv_w  = (const float*)d_in[2];
    const float* conv_b  = (const float*)d_in[3];
    const float* fc_w    = (const float*)d_in[4];
    const float* fc_b    = (const float*)d_in[5];
    const float* mu_w    = (const float*)d_in[6];
    const float* mu_b    = (const float*)d_in[7];
    const float* cb      = (const float*)d_in[8];
    float* out = (float*)d_out;

    cudaFuncSetAttribute(main_kernel,
                         cudaFuncAttributeMaxDynamicSharedMemorySize, SMEM_BYTES);

    setup_kernel<<<1, 256>>>(fc_b, mu_w, mu_b, cb);
    detect_kernel<<<(BS + 255) / 256, 256>>>((const unsigned char*)mask, BS);
    wfuse_kernel<<<KPAD / 4, 128>>>(fc_w, mu_w);
    main_kernel<<<NBLK, THR, SMEM_BYTES>>>(pr, mask, conv_w, conv_b, cb, out);
    final_kernel<<<1, 32>>>(out);
}

// round 11
// speedup vs baseline: 1.7053x; 1.6523x over previous
#include <cuda_runtime.h>
#include <cuda_fp16.h>
#include <math.h>
#include <stdint.h>

// ----------------------------------------------------------------------------
// FuncPitchEncoder R10: scalar conv + single-plane fp16 HMMA [feat]x[W|U]
// -> approx mu (for cmt) + approx VQ scores; exact fp32 refinement of rows
// whose top-2 gap is within a sound fp16 error bound. idx exact; z=cb[idx].
// ----------------------------------------------------------------------------

#define BS      131072
#define LEN     128
#define NCH     10
#define CONVK   12
#define POOLN   29
#define FEATN   290
#define EMB     256
#define ZD      128
#define KC_     64
#define ROWS    128
#define NBLK    (BS / ROWS)
#define THR     512

#define KPAD    320                 // 20 k16 tiles
#define NBCOL   192                 // B' = [W(128) | U(64)]
#define NTILES  24                  // 192/8

// smem float offsets
#define FEATT_F   38280             // featT [290][132] (stays live to the end)
#define OFF_SCR   FEATT_F           // 38280*4 = 153120, 16B aligned
#define SCR_F     10240             // prs 8448 | afrag 4096u32 + bbuf 6144u32 | s_sc 8576
#define OFF_MISC  (OFF_SCR + SCR_F) // 48520
#define SMEM_F    (OFF_MISC + 612 + 192)
#define SMEM_BYTES (SMEM_F * 4)     // 197296 B

// ----------------------------- helpers --------------------------------------
#define MMA16816(d, a, b) \
    asm volatile("mma.sync.aligned.m16n8k16.row.col.f32.f16.f16.f32 " \
        "{%0,%1,%2,%3}, {%4,%5,%6,%7}, {%8,%9}, {%0,%1,%2,%3};" \
        : "+f"((d)[0]), "+f"((d)[1]), "+f"((d)[2]), "+f"((d)[3]) \
        : "r"((a)[0]), "r"((a)[1]), "r"((a)[2]), "r"((a)[3]), \
          "r"((b)[0]), "r"((b)[1]))

__device__ __forceinline__ void cpasync16(uint32_t sdst, const void* g) {
    asm volatile("cp.async.cg.shared.global [%0], [%1], 16;" :: "r"(sdst), "l"(g));
}
#define CPASYNC_COMMIT() asm volatile("cp.async.commit_group;")
#define CPASYNC_WAIT0()  asm volatile("cp.async.wait_group 0;")

__device__ __forceinline__ uint32_t smem_u32(const void* p) {
    uint32_t a;
    asm("{ .reg .u64 t; cvta.to.shared.u64 t, %1; cvt.u32.u64 %0, t; }"
        : "=r"(a) : "l"(p));
    return a;
}

// ----------------------------- device scratch -------------------------------
__device__ __align__(16) float g_W[KPAD * ZD];          // fp32 fused W [k][j]
__device__ __align__(16) float g_U[KC_ * KPAD];         // fp32 U[c][k] = W @ c
// B' fp16 fragments: [kt 20][ntile 24][lane 32][reg 2] u32
__device__ __align__(16) uint32_t g_Bfrag[20 * NTILES * 32 * 2];
__device__ float g_bf[ZD];
__device__ float g_cnorm[KC_];
__device__ float g_sq[KC_];                              // cnorm - 2*b.c
__device__ int   g_UmaxI;                                // max|U| as int bits
__device__ float g_csum;
__device__ int   g_counts[KC_];
__device__ int   g_mask_u8;

// ----------------------------- setup kernel ---------------------------------
__global__ void setup_kernel(const float* __restrict__ fc_b,
                             const float* __restrict__ mu_w,
                             const float* __restrict__ mu_b,
                             const float* __restrict__ cb)
{
    int t = threadIdx.x;
    if (t == 0) { g_csum = 0.f; g_mask_u8 = 0; g_UmaxI = 0; }
    if (t < KC_) g_counts[t] = 0;
    if (t < ZD) {
        float a = mu_b[t];
        for (int e = 0; e < EMB; e++) a = fmaf(mu_w[t * EMB + e], fc_b[e], a);
        g_bf[t] = a;
    }
    if (t >= 128 && t < 128 + KC_) {
        int k = t - 128;
        float a = 0.f;
        for (int z = 0; z < ZD; z++) { float c = cb[k * ZD + z]; a = fmaf(c, c, a); }
        g_cnorm[k] = a;
    }
}

// ------------------------- mask dtype detection -----------------------------
__global__ void detect_kernel(const unsigned char* __restrict__ m, int n)
{
    int i = blockIdx.x * blockDim.x + threadIdx.x;
    int f = 0;
    if (i < n && (i & 3)) f = (m[i] != 0);
    if (__any_sync(0xffffffffu, f)) {
        if ((threadIdx.x & 31) == 0) atomicOr(&g_mask_u8, 1);
    }
}

// ------------------- fused-W precompute + W-part fp16 frags ------------------
__global__ void wfuse_kernel(const float* __restrict__ fc_w,
                             const float* __restrict__ mu_w)
{
    __shared__ float colw[EMB * 4];
    int t = threadIdx.x;                 // j = 0..127
    int k0 = blockIdx.x * 4;
    for (int i = t; i < EMB * 4; i += 128) {
        int e = i >> 2, kk = i & 3, k = k0 + kk;
        colw[i] = (k < FEATN) ? fc_w[e * FEATN + k] : 0.f;
    }
    __syncthreads();
    float a[4] = {0.f, 0.f, 0.f, 0.f};
    const float* mr = mu_w + t * EMB;
    #pragma unroll 4
    for (int e = 0; e < EMB; e++) {
        float m = mr[e];
        a[0] = fmaf(m, colw[e * 4 + 0], a[0]);
        a[1] = fmaf(m, colw[e * 4 + 1], a[1]);
        a[2] = fmaf(m, colw[e * 4 + 2], a[2]);
        a[3] = fmaf(m, colw[e * 4 + 3], a[3]);
    }
    unsigned short* B16 = (unsigned short*)g_Bfrag;
    #pragma unroll
    for (int kk = 0; kk < 4; kk++) {
        int k = k0 + kk;                 // 0..319
        g_W[k * ZD + t] = a[kk];
        int gkt = k >> 4, klt = k & 15;
        int nt = t >> 3;                 // W cols -> ntiles 0..15
        int tB = ((t & 7) << 2) + ((klt & 7) >> 1);
        int regb = klt >> 3, half = klt & 1;
        B16[((((gkt * NTILES + nt) * 32 + tB) * 2 + regb) << 1) + half] =
            __half_as_ushort(__float2half_rn(a[kk]));
    }
}

// -------------------- U = W @ C^T, s_q, Umax, U-part frags -------------------
__global__ void u_kernel(const float* __restrict__ cb)
{
    __shared__ float cbs[128];
    __shared__ float red[4];
    int c = blockIdx.x, t = threadIdx.x;         // 128 threads
    cbs[t] = cb[c * ZD + t];
    __syncthreads();
    float localmax = 0.f;
    unsigned short* B16 = (unsigned short*)g_Bfrag;
    for (int k = t; k < KPAD; k += 128) {
        float acc = 0.f;
        if (k < FEATN) {
            const float* wr = g_W + k * ZD;
            #pragma unroll 4
            for (int z = 0; z < ZD; z++) acc = fmaf(wr[z], cbs[z], acc);
        }
        g_U[c * KPAD + k] = acc;
        localmax = fmaxf(localmax, fabsf(acc));
        int gkt = k >> 4, klt = k & 15;
        int nt = 16 + (c >> 3);                  // U cols -> ntiles 16..23
        int tB = ((c & 7) << 2) + ((klt & 7) >> 1);
        int regb = klt >> 3, half = klt & 1;
        B16[((((gkt * NTILES + nt) * 32 + tB) * 2 + regb) << 1) + half] =
            __half_as_ushort(__float2half_rn(acc));
    }
    atomicMax(&g_UmaxI, __float_as_int(localmax));
    float p = g_bf[t] * cbs[t];
    #pragma unroll
    for (int o = 16; o > 0; o >>= 1) p += __shfl_down_sync(0xffffffffu, p, o);
    if ((t & 31) == 0) red[t >> 5] = p;
    __syncthreads();
    if (t == 0) {
        float bc = red[0] + red[1] + red[2] + red[3];
        g_sq[c] = g_cnorm[c] - 2.f * bc;
    }
}

// --------------------------- conv worker (scalar, R6) ------------------------
__device__ __noinline__ void conv_item(const float* __restrict__ prs,
                                       float* __restrict__ featT,
                                       const float* __restrict__ s_convw,
                                       const float* __restrict__ s_convb,
                                       int item, int rowbase)
{
    int rl = item / NCH;
    int ch = item - rl * NCH;
    int rloc = rowbase + rl;
    float wr[CONVK];
    #pragma unroll
    for (int i = 0; i < CONVK; i++) wr[i] = s_convw[ch * CONVK + i];
    float bb = s_convb[ch];
    const float* prow = &prs[rl * 132];
    float* fp = &featT[ch * POOLN * 132 + rloc];
    float x[15];
    #pragma unroll
    for (int i = 0; i < 15; i++) x[i] = prow[i];
    #pragma unroll
    for (int p = 0; p < POOLN; p++) {
        float m = 0.f;                   // relu >= 0
        #pragma unroll
        for (int j = 0; j < 4; j++) {
            float acc = bb;
            #pragma unroll
            for (int tt = 0; tt < CONVK; tt++)
                acc = fmaf(x[j + tt], wr[tt], acc);
            m = fmaxf(m, acc);
        }
        fp[p * 132] = m;
        if (p < POOLN - 1) {
            #pragma unroll
            for (int i = 0; i < 11; i++) x[i] = x[i + 4];
            #pragma unroll
            for (int i = 0; i < 4; i++) x[11 + i] = prow[4 * p + 15 + i];
        }
    }
}

// ------------------------------ main kernel ---------------------------------
__global__ __launch_bounds__(THR, 1)
void main_kernel(const float* __restrict__ pr,
                 const void*  __restrict__ mask,
                 const float* __restrict__ conv_w,
                 const float* __restrict__ conv_b,
                 const float* __restrict__ cb,
                 float* __restrict__ out)
{
    extern __shared__ float sm[];
    float* featT    = sm;                       // [290][132] — live to the end
    float* scr      = sm + OFF_SCR;             // prs | afrag+bbuf | s_sc
    float* s_convw  = sm + OFF_MISC;            // 120
    float* s_convb  = s_convw + 120;            // 12
    float* s_bf     = s_convb + 12;             // 128
    float* s_sq     = s_bf + 128;               // 64
    float* s_red    = s_sq + 64;                // 32
    float* s_smu    = s_red + 32;               // 128
    float* s_sabs   = s_smu + 128;              // 128
    int*   s_idx    = (int*)(s_sabs + 128);     // 128
    int*   s_counts = s_idx + 128;              // 64

    const int t    = threadIdx.x;
    const int blk  = blockIdx.x;
    const int lane = t & 31;
    const int w    = t >> 5;
    const int mi   = w >> 2;                    // rows 32*mi
    const int ni   = w & 3;                     // cols 48*ni (6 ntiles)

    // ---- misc loads / zeroing ----
    for (int i = t; i < 120; i += THR) s_convw[i] = conv_w[i];
    if (t < NCH)  s_convb[t] = conv_b[t];
    if (t < ZD)  { s_bf[t] = g_bf[t]; s_smu[t] = 0.f; s_sabs[t] = 0.f; }
    if (t < KC_) { s_sq[t] = g_sq[t]; s_counts[t] = 0; }

    // =============== Phase 1: conv + relu + maxpool -> featT ===============
    float* prs = scr;                           // [64][132]
    for (int sub = 0; sub < 2; sub++) {
        int row0 = blk * ROWS + sub * 64;
        __syncthreads();
        const float4* src = (const float4*)(pr + (size_t)row0 * LEN);
        for (int i = t; i < 64 * 32; i += THR) {
            int rr = i >> 5, c4 = i & 31;
            *(float4*)&prs[rr * 132 + c4 * 4] = src[i];
        }
        __syncthreads();
        conv_item(prs, featT, s_convw, s_convb, t, sub * 64);
        if (t < 128) conv_item(prs, featT, s_convw, s_convb, t + THR, sub * 64);
    }
    __syncthreads();                            // featT complete, prs dead

    // =============== Phase 2: [feat] x [W|U] single-plane fp16 HMMA ========
    uint32_t* afrag = (uint32_t*)scr;               // 4096 u32 (16KB)
    uint32_t* bbuf  = (uint32_t*)(scr + 4096);      // 6144 u32 (24KB)
    const uint32_t bbuf_sa = smem_u32(sm) + (OFF_SCR + 4096) * 4;

    float d[2][6][4];
    #pragma unroll
    for (int i = 0; i < 2; i++)
        #pragma unroll
        for (int j = 0; j < 6; j++)
            #pragma unroll
            for (int q = 0; q < 4; q++) d[i][j][q] = 0.f;

    float sabsLoc = 0.f;
    const int r_mine = t & 127;

    for (int c = 0; c < 5; c++) {
        // async-load B' chunk (4 kt x 24 nt x 256B = 24576B)
        const char* bsrc = (const char*)g_Bfrag + (size_t)c * 24576;
        #pragma unroll
        for (int u = 0; u < 3; u++) {
            int i = t + u * THR;                // 0..1535
            cpasync16(bbuf_sa + i * 16, bsrc + i * 16);
        }
        CPASYNC_COMMIT();
        // convert featT chunk -> fp16 A frags (overlaps cp.async)
        #pragma unroll
        for (int s = 0; s < 8; s++) {
            int idx = s * THR + t;
            int kle = (idx >> 7) * 2;           // 0..62 even
            int k = c * 64 + kle;
            float v0 = (k     < FEATN) ? featT[k * 132 + r_mine]       : 0.f;
            float v1 = (k + 1 < FEATN) ? featT[(k + 1) * 132 + r_mine] : 0.f;
            sabsLoc += fabsf(v0) + fabsf(v1);
            __half2 hh = __floats2half2_rn(v0, v1);
            int ktl = kle >> 4, klt = kle & 15;
            int reg = ((r_mine & 15) >> 3) + ((klt >> 3) << 1);
            int tA  = ((r_mine & 7) << 2) + ((klt & 7) >> 1);
            int mt  = r_mine >> 4;
            afrag[((ktl * 8 + mt) << 7) + (tA << 2) + reg] = *(uint32_t*)&hh;
        }
        CPASYNC_WAIT0();
        __syncthreads();

        #pragma unroll
        for (int kt = 0; kt < 4; kt++) {
            uint32_t a[2][4];
            #pragma unroll
            for (int s2 = 0; s2 < 2; s2++) {
                uint4 aa = *(const uint4*)&afrag[((kt * 8 + mi * 2 + s2) << 7) + (lane << 2)];
                a[s2][0] = aa.x; a[s2][1] = aa.y; a[s2][2] = aa.z; a[s2][3] = aa.w;
            }
            uint32_t b[6][2];
            #pragma unroll
            for (int q = 0; q < 6; q++) {
                uint2 bb = *(const uint2*)&bbuf[((kt * NTILES + ni * 6 + q) * 32 + lane) * 2];
                b[q][0] = bb.x; b[q][1] = bb.y;
            }
            #pragma unroll
            for (int s2 = 0; s2 < 2; s2++)
                #pragma unroll
                for (int q = 0; q < 6; q++)
                    MMA16816(d[s2][q], a[s2], b[q]);
        }
        __syncthreads();                        // buffers reused next chunk
    }
    atomicAdd(&s_sabs[r_mine], sabsLoc);

    // =============== Epilogue: smu partials + approx scores ================
    float* s_sc = scr;                          // [128][67]
    {
        #pragma unroll
        for (int s2 = 0; s2 < 2; s2++)
            #pragma unroll
            for (int rh = 0; rh < 2; rh++) {
                int row = mi * 32 + (lane >> 2) + s2 * 16 + rh * 8;
                float smuP = 0.f;
                #pragma unroll
                for (int q = 0; q < 6; q++) {
                    int colb = ni * 48 + q * 8;
                    int col0 = colb + (lane & 3) * 2;
                    float v0 = d[s2][q][rh * 2 + 0];
                    float v1 = d[s2][q][rh * 2 + 1];
                    if (colb < 128) {
                        float m0 = v0 + s_bf[col0];
                        float m1 = v1 + s_bf[col0 + 1];
                        smuP = fmaf(m0, m0, smuP);
                        smuP = fmaf(m1, m1, smuP);
                    } else {
                        int cc = col0 - 128;
                        s_sc[row * 67 + cc]     = s_sq[cc]     - 2.f * v0;
                        s_sc[row * 67 + cc + 1] = s_sq[cc + 1] - 2.f * v1;
                    }
                }
                // reduce smuP over the 4 lanes sharing this row
                smuP += __shfl_xor_sync(0xffffffffu, smuP, 1);
                smuP += __shfl_xor_sync(0xffffffffu, smuP, 2);
                if ((lane & 3) == 0 && smuP != 0.f) atomicAdd(&s_smu[row], smuP);
            }
    }
    __syncthreads();

    // =============== Phase 3: argmin + sound exact refinement ==============
    const float umax = __int_as_float(g_UmaxI);
    float e_row = 0.f;
    if (t < ROWS) {
        const int r = t;
        float marg = s_sabs[r] * umax * (1.0f / 256.0f);   // 2B bound
        float bv = 3.4e38f; int bi = 0;
        for (int c = 0; c < KC_; c++) {
            float s = s_sc[r * 67 + c];
            if (s < bv) { bv = s; bi = c; }
        }
        int ncand = 0;
        float thr = bv + marg;
        for (int c = 0; c < KC_; c++) if (s_sc[r * 67 + c] <= thr) ncand++;
        if (ncand > 1) {
            float bev = 3.4e38f; int bei = 0;
            for (int c = 0; c < KC_; c++) {
                if (s_sc[r * 67 + c] > thr) continue;
                const float* Uc = g_U + c * KPAD;
                float a0 = 0.f, a1 = 0.f, a2 = 0.f, a3 = 0.f;
                int k = 0;
                for (; k + 3 < FEATN; k += 4) {
                    a0 = fmaf(featT[(k + 0) * 132 + r], __ldg(Uc + k + 0), a0);
                    a1 = fmaf(featT[(k + 1) * 132 + r], __ldg(Uc + k + 1), a1);
                    a2 = fmaf(featT[(k + 2) * 132 + r], __ldg(Uc + k + 2), a2);
                    a3 = fmaf(featT[(k + 3) * 132 + r], __ldg(Uc + k + 3), a3);
                }
                for (; k < FEATN; k++)
                    a0 = fmaf(featT[k * 132 + r], __ldg(Uc + k), a0);
                float ex = s_sq[c] - 2.f * ((a0 + a1) + (a2 + a3));
                if (ex < bev) { bev = ex; bei = c; }
            }
            bi = bei;
        }
        s_idx[r] = bi;
        e_row = s_smu[r] + s_sc[r * 67 + bi];   // ||mu - c_idx||^2 (approx, ok for cmt)
    }
    __syncthreads();

    // =============== Phase 4: commitment, counts, z output =================
    const int flag_u8 = g_mask_u8;
    int validrow = 0;
    if (t < ROWS) {
        int rg = blk * ROWS + t;
        validrow = flag_u8 ? (((const unsigned char*)mask)[rg] == 0)
                           : (((const int*)mask)[rg] == 0);
        if (validrow) atomicAdd(&s_counts[s_idx[t]], 1);
    }
    float v = (t < ROWS && validrow) ? e_row : 0.f;
    #pragma unroll
    for (int o = 16; o > 0; o >>= 1) v += __shfl_down_sync(0xffffffffu, v, o);
    if ((t & 31) == 0) s_red[t >> 5] = v;
    __syncthreads();
    if (t == 0) {
        float tot = 0.f;
        for (int ww = 0; ww < 16; ww++) tot += s_red[ww];
        atomicAdd(&g_csum, tot);
    }
    if (t < KC_ && s_counts[t]) atomicAdd(&g_counts[t], s_counts[t]);

    // z = codebook[idx], vectorized
    float4* out4 = (float4*)(out + (size_t)blk * (ROWS * ZD));
    const float4* cb4 = (const float4*)cb;
    for (int i = t; i < ROWS * ZD / 4; i += THR) {
        int r = i >> 5, z4 = i & 31;
        out4[i] = cb4[s_idx[r] * 32 + z4];
    }
}

// ------------------------------ finalize ------------------------------------
__global__ void final_kernel(float* __restrict__ out)
{
    if (threadIdx.x == 0) {
        int nvi = 0;
        for (int k = 0; k < KC_; k++) nvi += g_counts[k];
        float nv = fmaxf((float)nvi, 1.f);
        float H = 0.f;
        for (int k = 0; k < KC_; k++) {
            float p = (float)g_counts[k] / nv;
            H += p * logf(p + 1e-10f);
        }
        out[(long)BS * ZD]     = 0.25f * g_csum / (nv * (float)ZD);
        out[(long)BS * ZD + 1] = expf(-H);
    }
}

// ------------------------------- launcher -----------------------------------
extern "C" void kernel_launch(void* const* d_in, const int* in_sizes, int n_in,
                              void* d_out, int out_size)
{
    const float* pr      = (const float*)d_in[0];
    const void*  mask    = d_in[1];
    const float* conv_w  = (const float*)d_in[2];
    const float* conv_b  = (const float*)d_in[3];
    const float* fc_w    = (const float*)d_in[4];
    const float* fc_b    = (const float*)d_in[5];
    const float* mu_w    = (const float*)d_in[6];
    const float* mu_b    = (const float*)d_in[7];
    const float* cb      = (const float*)d_in[8];
    float* out = (float*)d_out;

    cudaFuncSetAttribute(main_kernel,
                         cudaFuncAttributeMaxDynamicSharedMemorySize, SMEM_BYTES);

    setup_kernel<<<1, 256>>>(fc_b, mu_w, mu_b, cb);
    detect_kernel<<<(BS + 255) / 256, 256>>>((const unsigned char*)mask, BS);
    wfuse_kernel<<<KPAD / 4, 128>>>(fc_w, mu_w);
    u_kernel<<<KC_, 128>>>(cb);
    main_kernel<<<NBLK, THR, SMEM_BYTES>>>(pr, mask, conv_w, conv_b, cb, out);
    final_kernel<<<1, 32>>>(out);
}

// round 12
// speedup vs baseline: 2.5161x; 1.4754x over previous
#include <cuda_runtime.h>
#include <cuda_fp16.h>
#include <math.h>
#include <stdint.h>

// ----------------------------------------------------------------------------
// FuncPitchEncoder R11: 64-row blocks, 2 CTAs/SM (occ 2x), fp16 HMMA [feat]x[W|U]
// with exact fp32 refinement; parallelized u_kernel.
// ----------------------------------------------------------------------------

#define BS      131072
#define LEN     128
#define NCH     10
#define CONVK   12
#define POOLN   29
#define FEATN   290
#define EMB     256
#define ZD      128
#define KC_     64
#define ROWS    64
#define NBLK    (BS / ROWS)          // 2048
#define THR     384

#define KPAD    320                  // 20 k16 tiles
#define NTILES  24                   // 192 cols / 8

#define FSTR    66                   // featT row stride (64 rows + pad)

// smem float offsets
#define FEATT_F   (FEATN * FSTR)     // 19140
#define OFF_SCR   FEATT_F            // byte 76560, 16B aligned
#define SCR_F     8192               // prs 4224 | afrag 2048u32 + bbuf 6144u32 | s_sc 4288
#define OFF_MISC  (OFF_SCR + SCR_F)  // 27332
#define SMEM_F    (OFF_MISC + 468 + 128)
#define SMEM_BYTES (SMEM_F * 4)      // 111712 B -> 2 CTAs/SM

// ----------------------------- helpers --------------------------------------
#define MMA16816(d, a, b) \
    asm volatile("mma.sync.aligned.m16n8k16.row.col.f32.f16.f16.f32 " \
        "{%0,%1,%2,%3}, {%4,%5,%6,%7}, {%8,%9}, {%0,%1,%2,%3};" \
        : "+f"((d)[0]), "+f"((d)[1]), "+f"((d)[2]), "+f"((d)[3]) \
        : "r"((a)[0]), "r"((a)[1]), "r"((a)[2]), "r"((a)[3]), \
          "r"((b)[0]), "r"((b)[1]))

__device__ __forceinline__ void cpasync16(uint32_t sdst, const void* g) {
    asm volatile("cp.async.cg.shared.global [%0], [%1], 16;" :: "r"(sdst), "l"(g));
}
#define CPASYNC_COMMIT() asm volatile("cp.async.commit_group;")
#define CPASYNC_WAIT0()  asm volatile("cp.async.wait_group 0;")

__device__ __forceinline__ uint32_t smem_u32(const void* p) {
    uint32_t a;
    asm("{ .reg .u64 t; cvta.to.shared.u64 t, %1; cvt.u32.u64 %0, t; }"
        : "=r"(a) : "l"(p));
    return a;
}

// ----------------------------- device scratch -------------------------------
__device__ __align__(16) float g_W[KPAD * ZD];          // fp32 fused W [k][j]
__device__ __align__(16) float g_U[KC_ * KPAD];         // fp32 U[c][k]
// B' fp16 fragments: [kt 20][ntile 24][lane 32][reg 2] u32
__device__ __align__(16) uint32_t g_Bfrag[20 * NTILES * 32 * 2];
__device__ float g_bf[ZD];
__device__ float g_cnorm[KC_];
__device__ float g_sq[KC_];
__device__ int   g_UmaxI;
__device__ float g_csum;
__device__ int   g_counts[KC_];
__device__ int   g_mask_u8;

// ----------------------------- setup kernel ---------------------------------
__global__ void setup_kernel(const float* __restrict__ fc_b,
                             const float* __restrict__ mu_w,
                             const float* __restrict__ mu_b,
                             const float* __restrict__ cb)
{
    int t = threadIdx.x;
    if (t == 0) { g_csum = 0.f; g_mask_u8 = 0; g_UmaxI = 0; }
    if (t < KC_) g_counts[t] = 0;
    if (t < ZD) {
        float a = mu_b[t];
        for (int e = 0; e < EMB; e++) a = fmaf(mu_w[t * EMB + e], fc_b[e], a);
        g_bf[t] = a;
    }
    if (t >= 128 && t < 128 + KC_) {
        int k = t - 128;
        float a = 0.f;
        for (int z = 0; z < ZD; z++) { float c = cb[k * ZD + z]; a = fmaf(c, c, a); }
        g_cnorm[k] = a;
    }
}

// ------------------------- mask dtype detection -----------------------------
__global__ void detect_kernel(const unsigned char* __restrict__ m, int n)
{
    int i = blockIdx.x * blockDim.x + threadIdx.x;
    int f = 0;
    if (i < n && (i & 3)) f = (m[i] != 0);
    if (__any_sync(0xffffffffu, f)) {
        if ((threadIdx.x & 31) == 0) atomicOr(&g_mask_u8, 1);
    }
}

// ------------------- fused-W precompute + W-part fp16 frags ------------------
__global__ void wfuse_kernel(const float* __restrict__ fc_w,
                             const float* __restrict__ mu_w)
{
    __shared__ float colw[EMB * 4];
    int t = threadIdx.x;                 // j = 0..127
    int k0 = blockIdx.x * 4;
    for (int i = t; i < EMB * 4; i += 128) {
        int e = i >> 2, kk = i & 3, k = k0 + kk;
        colw[i] = (k < FEATN) ? fc_w[e * FEATN + k] : 0.f;
    }
    __syncthreads();
    float a[4] = {0.f, 0.f, 0.f, 0.f};
    const float* mr = mu_w + t * EMB;
    #pragma unroll 4
    for (int e = 0; e < EMB; e++) {
        float m = mr[e];
        a[0] = fmaf(m, colw[e * 4 + 0], a[0]);
        a[1] = fmaf(m, colw[e * 4 + 1], a[1]);
        a[2] = fmaf(m, colw[e * 4 + 2], a[2]);
        a[3] = fmaf(m, colw[e * 4 + 3], a[3]);
    }
    unsigned short* B16 = (unsigned short*)g_Bfrag;
    #pragma unroll
    for (int kk = 0; kk < 4; kk++) {
        int k = k0 + kk;                 // 0..319
        g_W[k * ZD + t] = a[kk];
        int gkt = k >> 4, klt = k & 15;
        int nt = t >> 3;
        int tB = ((t & 7) << 2) + ((klt & 7) >> 1);
        int regb = klt >> 3, half = klt & 1;
        B16[((((gkt * NTILES + nt) * 32 + tB) * 2 + regb) << 1) + half] =
            __half_as_ushort(__float2half_rn(a[kk]));
    }
}

// -------------------- U = W @ C^T, s_q, Umax, U-part frags -------------------
// <<<64, 320>>>: one thread per k, float4 W loads, 4-way ILP.
__global__ void u_kernel(const float* __restrict__ cb)
{
    __shared__ float cbs[128];
    __shared__ float red[4];
    int c = blockIdx.x, t = threadIdx.x;
    if (t < 128) cbs[t] = cb[c * ZD + t];
    __syncthreads();
    unsigned short* B16 = (unsigned short*)g_Bfrag;
    float localmax = 0.f;
    {
        int k = t;                               // 0..319
        float acc = 0.f;
        if (k < FEATN) {
            const float4* wr = (const float4*)(g_W + k * ZD);
            float a0 = 0.f, a1 = 0.f, a2 = 0.f, a3 = 0.f;
            #pragma unroll 8
            for (int z4 = 0; z4 < 32; z4++) {
                float4 wv = wr[z4];
                a0 = fmaf(wv.x, cbs[z4 * 4 + 0], a0);
                a1 = fmaf(wv.y, cbs[z4 * 4 + 1], a1);
                a2 = fmaf(wv.z, cbs[z4 * 4 + 2], a2);
                a3 = fmaf(wv.w, cbs[z4 * 4 + 3], a3);
            }
            acc = (a0 + a1) + (a2 + a3);
        }
        g_U[c * KPAD + k] = acc;
        localmax = fabsf(acc);
        int gkt = k >> 4, klt = k & 15;
        int nt = 16 + (c >> 3);
        int tB = ((c & 7) << 2) + ((klt & 7) >> 1);
        int regb = klt >> 3, half = klt & 1;
        B16[((((gkt * NTILES + nt) * 32 + tB) * 2 + regb) << 1) + half] =
            __half_as_ushort(__float2half_rn(acc));
    }
    #pragma unroll
    for (int o = 16; o > 0; o >>= 1)
        localmax = fmaxf(localmax, __shfl_xor_sync(0xffffffffu, localmax, o));
    if ((t & 31) == 0) atomicMax(&g_UmaxI, __float_as_int(localmax));
    if (t < 128) {
        float p = g_bf[t] * cbs[t];
        #pragma unroll
        for (int o = 16; o > 0; o >>= 1) p += __shfl_down_sync(0xffffffffu, p, o);
        if ((t & 31) == 0) red[t >> 5] = p;
    }
    __syncthreads();
    if (t == 0) {
        float bc = red[0] + red[1] + red[2] + red[3];
        g_sq[c] = g_cnorm[c] - 2.f * bc;
    }
}

// --------------------------- conv worker (scalar) ----------------------------
__device__ __noinline__ void conv_item(const float* __restrict__ prs,
                                       float* __restrict__ featT,
                                       const float* __restrict__ s_convw,
                                       const float* __restrict__ s_convb,
                                       int item, int rowbase)
{
    int rl = item / NCH;
    int ch = item - rl * NCH;
    int rloc = rowbase + rl;
    float wr[CONVK];
    #pragma unroll
    for (int i = 0; i < CONVK; i++) wr[i] = s_convw[ch * CONVK + i];
    float bb = s_convb[ch];
    const float* prow = &prs[rl * 132];
    float* fp = &featT[ch * POOLN * FSTR + rloc];
    float x[15];
    #pragma unroll
    for (int i = 0; i < 15; i++) x[i] = prow[i];
    #pragma unroll
    for (int p = 0; p < POOLN; p++) {
        float m = 0.f;                   // relu >= 0
        #pragma unroll
        for (int j = 0; j < 4; j++) {
            float acc = bb;
            #pragma unroll
            for (int tt = 0; tt < CONVK; tt++)
                acc = fmaf(x[j + tt], wr[tt], acc);
            m = fmaxf(m, acc);
        }
        fp[p * FSTR] = m;
        if (p < POOLN - 1) {
            #pragma unroll
            for (int i = 0; i < 11; i++) x[i] = x[i + 4];
            #pragma unroll
            for (int i = 0; i < 4; i++) x[11 + i] = prow[4 * p + 15 + i];
        }
    }
}

// ------------------------------ main kernel ---------------------------------
__global__ __launch_bounds__(THR, 2)
void main_kernel(const float* __restrict__ pr,
                 const void*  __restrict__ mask,
                 const float* __restrict__ conv_w,
                 const float* __restrict__ conv_b,
                 const float* __restrict__ cb,
                 float* __restrict__ out)
{
    extern __shared__ float sm[];
    float* featT    = sm;                       // [290][66] — live to the end
    float* scr      = sm + OFF_SCR;             // prs | afrag+bbuf | s_sc
    float* s_convw  = sm + OFF_MISC;            // 120
    float* s_convb  = s_convw + 120;            // 12
    float* s_bf     = s_convb + 12;             // 128
    float* s_sq     = s_bf + 128;               // 64
    float* s_red    = s_sq + 64;                // 16
    float* s_smu    = s_red + 16;               // 64
    float* s_sabs   = s_smu + 64;               // 64
    int*   s_idx    = (int*)(s_sabs + 64);      // 64
    int*   s_counts = s_idx + 64;               // 64

    const int t    = threadIdx.x;
    const int blk  = blockIdx.x;
    const int lane = t & 31;
    const int w    = t >> 5;                    // 0..11
    const int mi   = w / 6;                     // 0..1: rows 32*mi
    const int ni   = w % 6;                     // 0..5: ntiles ni*4..ni*4+3

    // ---- misc loads / zeroing ----
    for (int i = t; i < 120; i += THR) s_convw[i] = conv_w[i];
    if (t < NCH)  s_convb[t] = conv_b[t];
    if (t < ZD)   s_bf[t] = g_bf[t];
    if (t < ROWS) { s_smu[t] = 0.f; s_sabs[t] = 0.f; }
    if (t < KC_) { s_sq[t] = g_sq[t]; s_counts[t] = 0; }

    // =============== Phase 1: conv + relu + maxpool -> featT ===============
    float* prs = scr;                           // [32][132]
    for (int sub = 0; sub < 2; sub++) {
        int row0 = blk * ROWS + sub * 32;
        __syncthreads();
        const float4* src = (const float4*)(pr + (size_t)row0 * LEN);
        for (int i = t; i < 32 * 32; i += THR) {
            int rr = i >> 5, c4 = i & 31;
            *(float4*)&prs[rr * 132 + c4 * 4] = src[i];
        }
        __syncthreads();
        if (t < 320) conv_item(prs, featT, s_convw, s_convb, t, sub * 32);
    }
    __syncthreads();                            // featT complete, prs dead

    // =============== Phase 2: [feat] x [W|U] fp16 HMMA =====================
    uint32_t* afrag = (uint32_t*)scr;               // 2048 u32 (8KB)
    uint32_t* bbuf  = (uint32_t*)(scr + 2048);      // 6144 u32 (24KB)
    const uint32_t bbuf_sa = smem_u32(sm) + (OFF_SCR + 2048) * 4;

    float d[2][4][4];
    #pragma unroll
    for (int i = 0; i < 2; i++)
        #pragma unroll
        for (int j = 0; j < 4; j++)
            #pragma unroll
            for (int q = 0; q < 4; q++) d[i][j][q] = 0.f;

    for (int c = 0; c < 5; c++) {
        // async-load B' chunk (4 kt x 24 nt x 256B = 24576B = 1536 x 16B)
        const char* bsrc = (const char*)g_Bfrag + (size_t)c * 24576;
        #pragma unroll
        for (int u = 0; u < 4; u++) {
            int i = t + u * THR;                // 0..1535
            cpasync16(bbuf_sa + i * 16, bsrc + i * 16);
        }
        CPASYNC_COMMIT();
        // convert featT chunk -> fp16 A frags (overlaps cp.async)
        for (int i = t; i < 2048; i += THR) {
            int r   = i & 63;
            int kle = (i >> 6) * 2;             // 0..62 even
            int k = c * 64 + kle;
            float v0 = (k     < FEATN) ? featT[k * FSTR + r]       : 0.f;
            float v1 = (k + 1 < FEATN) ? featT[(k + 1) * FSTR + r] : 0.f;
            atomicAdd(&s_sabs[r], fabsf(v0) + fabsf(v1));
            __half2 hh = __floats2half2_rn(v0, v1);
            int ktl = kle >> 4, klt = kle & 15;
            int reg = ((r & 15) >> 3) + ((klt >> 3) << 1);
            int tA  = ((r & 7) << 2) + ((klt & 7) >> 1);
            int mt  = r >> 4;
            afrag[((ktl * 4 + mt) << 7) + (tA << 2) + reg] = *(uint32_t*)&hh;
        }
        CPASYNC_WAIT0();
        __syncthreads();

        #pragma unroll
        for (int kt = 0; kt < 4; kt++) {
            uint32_t a[2][4];
            #pragma unroll
            for (int s2 = 0; s2 < 2; s2++) {
                uint4 aa = *(const uint4*)&afrag[((kt * 4 + mi * 2 + s2) << 7) + (lane << 2)];
                a[s2][0] = aa.x; a[s2][1] = aa.y; a[s2][2] = aa.z; a[s2][3] = aa.w;
            }
            uint32_t b[4][2];
            #pragma unroll
            for (int q = 0; q < 4; q++) {
                uint2 bb = *(const uint2*)&bbuf[((kt * NTILES + ni * 4 + q) * 32 + lane) * 2];
                b[q][0] = bb.x; b[q][1] = bb.y;
            }
            #pragma unroll
            for (int s2 = 0; s2 < 2; s2++)
                #pragma unroll
                for (int q = 0; q < 4; q++)
                    MMA16816(d[s2][q], a[s2], b[q]);
        }
        __syncthreads();                        // buffers reused next chunk
    }

    // =============== Epilogue: smu partials + approx scores ================
    float* s_sc = scr;                          // [64][67]
    {
        #pragma unroll
        for (int s2 = 0; s2 < 2; s2++)
            #pragma unroll
            for (int rh = 0; rh < 2; rh++) {
                int row = mi * 32 + (lane >> 2) + s2 * 16 + rh * 8;
                float smuP = 0.f;
                #pragma unroll
                for (int q = 0; q < 4; q++) {
                    int colb = (ni * 4 + q) * 8;
                    int col0 = colb + (lane & 3) * 2;
                    float v0 = d[s2][q][rh * 2 + 0];
                    float v1 = d[s2][q][rh * 2 + 1];
                    if (colb < 128) {
                        float m0 = v0 + s_bf[col0];
                        float m1 = v1 + s_bf[col0 + 1];
                        smuP = fmaf(m0, m0, smuP);
                        smuP = fmaf(m1, m1, smuP);
                    } else {
                        int cc = col0 - 128;
                        s_sc[row * 67 + cc]     = s_sq[cc]     - 2.f * v0;
                        s_sc[row * 67 + cc + 1] = s_sq[cc + 1] - 2.f * v1;
                    }
                }
                smuP += __shfl_xor_sync(0xffffffffu, smuP, 1);
                smuP += __shfl_xor_sync(0xffffffffu, smuP, 2);
                if ((lane & 3) == 0 && smuP != 0.f) atomicAdd(&s_smu[row], smuP);
            }
    }
    __syncthreads();

    // =============== Phase 3: argmin + sound exact refinement ==============
    const float umax = __int_as_float(g_UmaxI);
    float e_row = 0.f;
    if (t < ROWS) {
        const int r = t;
        float marg = s_sabs[r] * umax * (1.0f / 256.0f);   // 2B bound
        float bv = 3.4e38f; int bi = 0;
        for (int c = 0; c < KC_; c++) {
            float s = s_sc[r * 67 + c];
            if (s < bv) { bv = s; bi = c; }
        }
        int ncand = 0;
        float thr = bv + marg;
        for (int c = 0; c < KC_; c++) if (s_sc[r * 67 + c] <= thr) ncand++;
        if (ncand > 1) {
            float bev = 3.4e38f; int bei = 0;
            for (int c = 0; c < KC_; c++) {
                if (s_sc[r * 67 + c] > thr) continue;
                const float* Uc = g_U + c * KPAD;
                float a0 = 0.f, a1 = 0.f, a2 = 0.f, a3 = 0.f;
                int k = 0;
                for (; k + 3 < FEATN; k += 4) {
                    a0 = fmaf(featT[(k + 0) * FSTR + r], __ldg(Uc + k + 0), a0);
                    a1 = fmaf(featT[(k + 1) * FSTR + r], __ldg(Uc + k + 1), a1);
                    a2 = fmaf(featT[(k + 2) * FSTR + r], __ldg(Uc + k + 2), a2);
                    a3 = fmaf(featT[(k + 3) * FSTR + r], __ldg(Uc + k + 3), a3);
                }
                for (; k < FEATN; k++)
                    a0 = fmaf(featT[k * FSTR + r], __ldg(Uc + k), a0);
                float ex = s_sq[c] - 2.f * ((a0 + a1) + (a2 + a3));
                if (ex < bev) { bev = ex; bei = c; }
            }
            bi = bei;
        }
        s_idx[r] = bi;
        e_row = s_smu[r] + s_sc[r * 67 + bi];
    }
    __syncthreads();

    // =============== Phase 4: commitment, counts, z output =================
    const int flag_u8 = g_mask_u8;
    int validrow = 0;
    if (t < ROWS) {
        int rg = blk * ROWS + t;
        validrow = flag_u8 ? (((const unsigned char*)mask)[rg] == 0)
                           : (((const int*)mask)[rg] == 0);
        if (validrow) atomicAdd(&s_counts[s_idx[t]], 1);
    }
    float v = (t < ROWS && validrow) ? e_row : 0.f;
    #pragma unroll
    for (int o = 16; o > 0; o >>= 1) v += __shfl_down_sync(0xffffffffu, v, o);
    if ((t & 31) == 0) s_red[t >> 5] = v;
    __syncthreads();
    if (t == 0) {
        float tot = 0.f;
        for (int ww = 0; ww < 12; ww++) tot += s_red[ww];
        atomicAdd(&g_csum, tot);
    }
    if (t < KC_ && s_counts[t]) atomicAdd(&g_counts[t], s_counts[t]);

    // z = codebook[idx], vectorized
    float4* out4 = (float4*)(out + (size_t)blk * (ROWS * ZD));
    const float4* cb4 = (const float4*)cb;
    for (int i = t; i < ROWS * ZD / 4; i += THR) {
        int r = i >> 5, z4 = i & 31;
        out4[i] = cb4[s_idx[r] * 32 + z4];
    }
}

// ------------------------------ finalize ------------------------------------
__global__ void final_kernel(float* __restrict__ out)
{
    if (threadIdx.x == 0) {
        int nvi = 0;
        for (int k = 0; k < KC_; k++) nvi += g_counts[k];
        float nv = fmaxf((float)nvi, 1.f);
        float H = 0.f;
        for (int k = 0; k < KC_; k++) {
            float p = (float)g_counts[k] / nv;
            H += p * logf(p + 1e-10f);
        }
        out[(long)BS * ZD]     = 0.25f * g_csum / (nv * (float)ZD);
        out[(long)BS * ZD + 1] = expf(-H);
    }
}

// ------------------------------- launcher -----------------------------------
extern "C" void kernel_launch(void* const* d_in, const int* in_sizes, int n_in,
                              void* d_out, int out_size)
{
    const float* pr      = (const float*)d_in[0];
    const void*  mask    = d_in[1];
    const float* conv_w  = (const float*)d_in[2];
    const float* conv_b  = (const float*)d_in[3];
    const float* fc_w    = (const float*)d_in[4];
    const float* fc_b    = (const float*)d_in[5];
    const float* mu_w    = (const float*)d_in[6];
    const float* mu_b    = (const float*)d_in[7];
    const float* cb      = (const float*)d_in[8];
    float* out = (float*)d_out;

    cudaFuncSetAttribute(main_kernel,
                         cudaFuncAttributeMaxDynamicSharedMemorySize, SMEM_BYTES);

    setup_kernel<<<1, 256>>>(fc_b, mu_w, mu_b, cb);
    detect_kernel<<<(BS + 255) / 256, 256>>>((const unsigned char*)mask, BS);
    wfuse_kernel<<<KPAD / 4, 128>>>(fc_w, mu_w);
    u_kernel<<<KC_, KPAD>>>(cb);
    main_kernel<<<NBLK, THR, SMEM_BYTES>>>(pr, mask, conv_w, conv_b, cb, out);
    final_kernel<<<1, 32>>>(out);
}

// round 14
// speedup vs baseline: 2.5732x; 1.0227x over previous
#include <cuda_runtime.h>
#include <cuda_fp16.h>
#include <math.h>
#include <stdint.h>

// ----------------------------------------------------------------------------
// FuncPitchEncoder R12: R11 architecture (64-row blocks, 2 CTAs/SM, fp16 HMMA
// [feat]x[W|U] + exact fp32 refinement) with fixed-overhead removal:
// u_kernel folded into wfuse, setup+detect merged, sabs moved into conv.
// ----------------------------------------------------------------------------

#define BS      131072
#define LEN     128
#define NCH     10
#define CONVK   12
#define POOLN   29
#define FEATN   290
#define EMB     256
#define ZD      128
#define KC_     64
#define ROWS    64
#define NBLK    (BS / ROWS)          // 2048
#define THR     384

#define KPAD    320                  // 20 k16 tiles
#define NTILES  24                   // 192 cols / 8
#define FSTR    66                   // featT row stride

// smem float offsets
#define FEATT_F   (FEATN * FSTR)     // 19140
#define OFF_SCR   FEATT_F
#define SCR_F     8192               // prs 4224 | afrag 2048u32 + bbuf 6144u32 | s_sc 4288
#define OFF_MISC  (OFF_SCR + SCR_F)
#define SMEM_F    (OFF_MISC + 468 + 128)
#define SMEM_BYTES (SMEM_F * 4)      // 111712 B -> 2 CTAs/SM

// ----------------------------- helpers --------------------------------------
#define MMA16816(d, a, b) \
    asm volatile("mma.sync.aligned.m16n8k16.row.col.f32.f16.f16.f32 " \
        "{%0,%1,%2,%3}, {%4,%5,%6,%7}, {%8,%9}, {%0,%1,%2,%3};" \
        : "+f"((d)[0]), "+f"((d)[1]), "+f"((d)[2]), "+f"((d)[3]) \
        : "r"((a)[0]), "r"((a)[1]), "r"((a)[2]), "r"((a)[3]), \
          "r"((b)[0]), "r"((b)[1]))

__device__ __forceinline__ void cpasync16(uint32_t sdst, const void* g) {
    asm volatile("cp.async.cg.shared.global [%0], [%1], 16;" :: "r"(sdst), "l"(g));
}
#define CPASYNC_COMMIT() asm volatile("cp.async.commit_group;")
#define CPASYNC_WAIT0()  asm volatile("cp.async.wait_group 0;")

__device__ __forceinline__ uint32_t smem_u32(const void* p) {
    uint32_t a;
    asm("{ .reg .u64 t; cvta.to.shared.u64 t, %1; cvt.u32.u64 %0, t; }"
        : "=r"(a) : "l"(p));
    return a;
}

// ----------------------------- device scratch -------------------------------
__device__ __align__(16) float g_W[KPAD * ZD];          // fp32 fused W [k][j]
__device__ __align__(16) float g_U[KC_ * KPAD];         // fp32 U[c][k]
// B' fp16 fragments: [kt 20][ntile 24][lane 32][reg 2] u32
__device__ __align__(16) uint32_t g_Bfrag[20 * NTILES * 32 * 2];
__device__ float g_bf[ZD];
__device__ float g_cnorm[KC_];
__device__ float g_sq[KC_];
__device__ int   g_UmaxI;
__device__ float g_csum;
__device__ int   g_counts[KC_];
__device__ int   g_mask_u8;

// ---------------------- setup + detect (2 blocks) ----------------------------
__global__ void setup_kernel(const float* __restrict__ fc_b,
                             const float* __restrict__ mu_w,
                             const float* __restrict__ mu_b,
                             const float* __restrict__ cb,
                             const unsigned char* __restrict__ m, int n)
{
    int t = threadIdx.x;
    if (blockIdx.x == 1) {
        // mask dtype detection: int32 0/1 has zero bytes at offset%4 != 0
        int f = 0;
        for (int i = t; i < n; i += 512)
            if (i & 3) f |= (m[i] != 0);
        if (__any_sync(0xffffffffu, f)) {
            if ((t & 31) == 0) atomicOr(&g_mask_u8, 1);
        }
        return;
    }
    if (t == 0) { g_csum = 0.f; g_UmaxI = 0; }
    if (t < KC_) g_counts[t] = 0;
    if (t < ZD) {
        float a = mu_b[t];
        for (int e = 0; e < EMB; e++) a = fmaf(mu_w[t * EMB + e], fc_b[e], a);
        g_bf[t] = a;
    }
    if (t >= 128 && t < 128 + KC_) {
        int k = t - 128;
        float a = 0.f;
        for (int z = 0; z < ZD; z++) { float c = cb[k * ZD + z]; a = fmaf(c, c, a); }
        g_cnorm[k] = a;
    }
    __syncthreads();
    if (t < KC_) {
        float bc = 0.f;
        const float* cc = cb + t * ZD;
        #pragma unroll 4
        for (int z = 0; z < ZD; z++) bc = fmaf(g_bf[z], cc[z], bc);
        g_sq[t] = g_cnorm[t] - 2.f * bc;
    }
}

// --------- fused-W precompute + W-frags + U = W@C^T + U-frags + Umax --------
__global__ void wfuse_kernel(const float* __restrict__ fc_w,
                             const float* __restrict__ mu_w,
                             const float* __restrict__ cb)
{
    __shared__ float colw[EMB * 4];      // 4096 f
    __shared__ float Wsm[4 * ZD];        // 512 f
    __shared__ float cbs[KC_ * ZD];      // 8192 f
    int t = threadIdx.x;                 // j = 0..127
    int k0 = blockIdx.x * 4;
    for (int i = t; i < EMB * 4; i += 128) {
        int e = i >> 2, kk = i & 3, k = k0 + kk;
        colw[i] = (k < FEATN) ? fc_w[e * FEATN + k] : 0.f;
    }
    for (int i = t; i < KC_ * ZD; i += 128) cbs[i] = cb[i];
    __syncthreads();
    float a[4] = {0.f, 0.f, 0.f, 0.f};
    const float* mr = mu_w + t * EMB;
    #pragma unroll 4
    for (int e = 0; e < EMB; e++) {
        float m = mr[e];
        a[0] = fmaf(m, colw[e * 4 + 0], a[0]);
        a[1] = fmaf(m, colw[e * 4 + 1], a[1]);
        a[2] = fmaf(m, colw[e * 4 + 2], a[2]);
        a[3] = fmaf(m, colw[e * 4 + 3], a[3]);
    }
    unsigned short* B16 = (unsigned short*)g_Bfrag;
    #pragma unroll
    for (int kk = 0; kk < 4; kk++) {
        int k = k0 + kk;                 // 0..319
        g_W[k * ZD + t] = a[kk];
        Wsm[kk * ZD + t] = a[kk];
        int gkt = k >> 4, klt = k & 15;
        int nt = t >> 3;                 // W cols -> ntiles 0..15
        int tB = ((t & 7) << 2) + ((klt & 7) >> 1);
        int regb = klt >> 3, half = klt & 1;
        B16[((((gkt * NTILES + nt) * 32 + tB) * 2 + regb) << 1) + half] =
            __half_as_ushort(__float2half_rn(a[kk]));
    }
    __syncthreads();
    // U part: 256 (c,kk) pairs over 128 threads (2 each)
    float localmax = 0.f;
    #pragma unroll
    for (int pp = 0; pp < 2; pp++) {
        int idx = t + pp * 128;          // 0..255
        int c  = idx & 63;
        int kk = idx >> 6;
        int k  = k0 + kk;
        const float* wr = Wsm + kk * ZD;
        const float* cc = cbs + c * ZD;
        float a0 = 0.f, a1 = 0.f, a2 = 0.f, a3 = 0.f;
        #pragma unroll 8
        for (int z = 0; z < ZD; z += 4) {
            a0 = fmaf(wr[z + 0], cc[z + 0], a0);
            a1 = fmaf(wr[z + 1], cc[z + 1], a1);
            a2 = fmaf(wr[z + 2], cc[z + 2], a2);
            a3 = fmaf(wr[z + 3], cc[z + 3], a3);
        }
        float acc = (a0 + a1) + (a2 + a3);
        g_U[c * KPAD + k] = acc;
        localmax = fmaxf(localmax, fabsf(acc));
        int gkt = k >> 4, klt = k & 15;
        int nt = 16 + (c >> 3);          // U cols -> ntiles 16..23
        int tB = ((c & 7) << 2) + ((klt & 7) >> 1);
        int regb = klt >> 3, half = klt & 1;
        B16[((((gkt * NTILES + nt) * 32 + tB) * 2 + regb) << 1) + half] =
            __half_as_ushort(__float2half_rn(acc));
    }
    #pragma unroll
    for (int o = 16; o > 0; o >>= 1)
        localmax = fmaxf(localmax, __shfl_xor_sync(0xffffffffu, localmax, o));
    if ((t & 31) == 0) atomicMax(&g_UmaxI, __float_as_int(localmax));
}

// --------------------------- conv worker (scalar) ----------------------------
// Also accumulates the row's feature sum (relu => |f| = f) for the error bound.
__device__ __noinline__ void conv_item(const float* __restrict__ prs,
                                       float* __restrict__ featT,
                                       float* __restrict__ s_sabs,
                                       const float* __restrict__ s_convw,
                                       const float* __restrict__ s_convb,
                                       int item, int rowbase)
{
    int rl = item / NCH;
    int ch = item - rl * NCH;
    int rloc = rowbase + rl;
    float wr[CONVK];
    #pragma unroll
    for (int i = 0; i < CONVK; i++) wr[i] = s_convw[ch * CONVK + i];
    float bb = s_convb[ch];
    const float* prow = &prs[rl * 132];
    float* fp = &featT[ch * POOLN * FSTR + rloc];
    float x[15];
    #pragma unroll
    for (int i = 0; i < 15; i++) x[i] = prow[i];
    float ssum = 0.f;
    #pragma unroll
    for (int p = 0; p < POOLN; p++) {
        float m = 0.f;                   // relu >= 0
        #pragma unroll
        for (int j = 0; j < 4; j++) {
            float acc = bb;
            #pragma unroll
            for (int tt = 0; tt < CONVK; tt++)
                acc = fmaf(x[j + tt], wr[tt], acc);
            m = fmaxf(m, acc);
        }
        fp[p * FSTR] = m;
        ssum += m;
        if (p < POOLN - 1) {
            #pragma unroll
            for (int i = 0; i < 11; i++) x[i] = x[i + 4];
            #pragma unroll
            for (int i = 0; i < 4; i++) x[11 + i] = prow[4 * p + 15 + i];
        }
    }
    atomicAdd(&s_sabs[rloc], ssum);
}

// ------------------------------ main kernel ---------------------------------
__global__ __launch_bounds__(THR, 2)
void main_kernel(const float* __restrict__ pr,
                 const void*  __restrict__ mask,
                 const float* __restrict__ conv_w,
                 const float* __restrict__ conv_b,
                 const float* __restrict__ cb,
                 float* __restrict__ out)
{
    extern __shared__ float sm[];
    float* featT    = sm;                       // [290][66] — live to the end
    float* scr      = sm + OFF_SCR;             // prs | afrag+bbuf | s_sc
    float* s_convw  = sm + OFF_MISC;            // 120
    float* s_convb  = s_convw + 120;            // 12
    float* s_bf     = s_convb + 12;             // 128
    float* s_sq     = s_bf + 128;               // 64
    float* s_red    = s_sq + 64;                // 16
    float* s_smu    = s_red + 16;               // 64
    float* s_sabs   = s_smu + 64;               // 64
    int*   s_idx    = (int*)(s_sabs + 64);      // 64
    int*   s_counts = s_idx + 64;               // 64

    const int t    = threadIdx.x;
    const int blk  = blockIdx.x;
    const int lane = t & 31;
    const int w    = t >> 5;                    // 0..11
    const int mi   = w / 6;                     // 0..1: rows 32*mi
    const int ni   = w % 6;                     // 0..5: ntiles ni*4..ni*4+3

    // ---- misc loads / zeroing ----
    for (int i = t; i < 120; i += THR) s_convw[i] = conv_w[i];
    if (t < NCH)  s_convb[t] = conv_b[t];
    if (t < ZD)   s_bf[t] = g_bf[t];
    if (t < ROWS) { s_smu[t] = 0.f; s_sabs[t] = 0.f; }
    if (t < KC_) { s_sq[t] = g_sq[t]; s_counts[t] = 0; }

    // =============== Phase 1: conv + relu + maxpool -> featT ===============
    float* prs = scr;                           // [32][132]
    for (int sub = 0; sub < 2; sub++) {
        int row0 = blk * ROWS + sub * 32;
        __syncthreads();
        const float4* src = (const float4*)(pr + (size_t)row0 * LEN);
        for (int i = t; i < 32 * 32; i += THR) {
            int rr = i >> 5, c4 = i & 31;
            *(float4*)&prs[rr * 132 + c4 * 4] = src[i];
        }
        __syncthreads();
        if (t < 320) conv_item(prs, featT, s_sabs, s_convw, s_convb, t, sub * 32);
    }
    __syncthreads();                            // featT complete, prs dead

    // =============== Phase 2: [feat] x [W|U] fp16 HMMA =====================
    uint32_t* afrag = (uint32_t*)scr;               // 2048 u32 (8KB)
    uint32_t* bbuf  = (uint32_t*)(scr + 2048);      // 6144 u32 (24KB)
    const uint32_t bbuf_sa = smem_u32(sm) + (OFF_SCR + 2048) * 4;

    float d[2][4][4];
    #pragma unroll
    for (int i = 0; i < 2; i++)
        #pragma unroll
        for (int j = 0; j < 4; j++)
            #pragma unroll
            for (int q = 0; q < 4; q++) d[i][j][q] = 0.f;

    for (int c = 0; c < 5; c++) {
        // async-load B' chunk (4 kt x 24 nt x 256B = 24576B = 1536 x 16B)
        const char* bsrc = (const char*)g_Bfrag + (size_t)c * 24576;
        #pragma unroll
        for (int u = 0; u < 4; u++) {
            int i = t + u * THR;                // 0..1535
            cpasync16(bbuf_sa + i * 16, bsrc + i * 16);
        }
        CPASYNC_COMMIT();
        // convert featT chunk -> fp16 A frags (overlaps cp.async)
        for (int i = t; i < 2048; i += THR) {
            int r   = i & 63;
            int kle = (i >> 6) * 2;             // 0..62 even
            int k = c * 64 + kle;
            float v0 = (k     < FEATN) ? featT[k * FSTR + r]       : 0.f;
            float v1 = (k + 1 < FEATN) ? featT[(k + 1) * FSTR + r] : 0.f;
            __half2 hh = __floats2half2_rn(v0, v1);
            int ktl = kle >> 4, klt = kle & 15;
            int reg = ((r & 15) >> 3) + ((klt >> 3) << 1);
            int tA  = ((r & 7) << 2) + ((klt & 7) >> 1);
            int mt  = r >> 4;
            afrag[((ktl * 4 + mt) << 7) + (tA << 2) + reg] = *(uint32_t*)&hh;
        }
        CPASYNC_WAIT0();
        __syncthreads();

        #pragma unroll
        for (int kt = 0; kt < 4; kt++) {
            uint32_t a[2][4];
            #pragma unroll
            for (int s2 = 0; s2 < 2; s2++) {
                uint4 aa = *(const uint4*)&afrag[((kt * 4 + mi * 2 + s2) << 7) + (lane << 2)];
                a[s2][0] = aa.x; a[s2][1] = aa.y; a[s2][2] = aa.z; a[s2][3] = aa.w;
            }
            uint32_t b[4][2];
            #pragma unroll
            for (int q = 0; q < 4; q++) {
                uint2 bb = *(const uint2*)&bbuf[((kt * NTILES + ni * 4 + q) * 32 + lane) * 2];
                b[q][0] = bb.x; b[q][1] = bb.y;
            }
            #pragma unroll
            for (int s2 = 0; s2 < 2; s2++)
                #pragma unroll
                for (int q = 0; q < 4; q++)
                    MMA16816(d[s2][q], a[s2], b[q]);
        }
        __syncthreads();                        // buffers reused next chunk
    }

    // =============== Epilogue: smu partials + approx scores ================
    float* s_sc = scr;                          // [64][67]
    {
        #pragma unroll
        for (int s2 = 0; s2 < 2; s2++)
            #pragma unroll
            for (int rh = 0; rh < 2; rh++) {
                int row = mi * 32 + (lane >> 2) + s2 * 16 + rh * 8;
                float smuP = 0.f;
                #pragma unroll
                for (int q = 0; q < 4; q++) {
                    int colb = (ni * 4 + q) * 8;
                    int col0 = colb + (lane & 3) * 2;
                    float v0 = d[s2][q][rh * 2 + 0];
                    float v1 = d[s2][q][rh * 2 + 1];
                    if (colb < 128) {
                        float m0 = v0 + s_bf[col0];
                        float m1 = v1 + s_bf[col0 + 1];
                        smuP = fmaf(m0, m0, smuP);
                        smuP = fmaf(m1, m1, smuP);
                    } else {
                        int cc = col0 - 128;
                        s_sc[row * 67 + cc]     = s_sq[cc]     - 2.f * v0;
                        s_sc[row * 67 + cc + 1] = s_sq[cc + 1] - 2.f * v1;
                    }
                }
                smuP += __shfl_xor_sync(0xffffffffu, smuP, 1);
                smuP += __shfl_xor_sync(0xffffffffu, smuP, 2);
                if ((lane & 3) == 0 && smuP != 0.f) atomicAdd(&s_smu[row], smuP);
            }
    }
    __syncthreads();

    // =============== Phase 3: argmin + sound exact refinement ==============
    const float umax = __int_as_float(g_UmaxI);
    float e_row = 0.f;
    if (t < ROWS) {
        const int r = t;
        float marg = s_sabs[r] * umax * (1.0f / 256.0f);   // 2B bound
        float bv = 3.4e38f; int bi = 0;
        for (int c = 0; c < KC_; c++) {
            float s = s_sc[r * 67 + c];
            if (s < bv) { bv = s; bi = c; }
        }
        int ncand = 0;
        float thr = bv + marg;
        for (int c = 0; c < KC_; c++) if (s_sc[r * 67 + c] <= thr) ncand++;
        if (ncand > 1) {
            float bev = 3.4e38f; int bei = 0;
            for (int c = 0; c < KC_; c++) {
                if (s_sc[r * 67 + c] > thr) continue;
                const float* Uc = g_U + c * KPAD;
                float a0 = 0.f, a1 = 0.f, a2 = 0.f, a3 = 0.f;
                int k = 0;
                for (; k + 3 < FEATN; k += 4) {
                    a0 = fmaf(featT[(k + 0) * FSTR + r], __ldg(Uc + k + 0), a0);
                    a1 = fmaf(featT[(k + 1) * FSTR + r], __ldg(Uc + k + 1), a1);
                    a2 = fmaf(featT[(k + 2) * FSTR + r], __ldg(Uc + k + 2), a2);
                    a3 = fmaf(featT[(k + 3) * FSTR + r], __ldg(Uc + k + 3), a3);
                }
                for (; k < FEATN; k++)
                    a0 = fmaf(featT[k * FSTR + r], __ldg(Uc + k), a0);
                float ex = s_sq[c] - 2.f * ((a0 + a1) + (a2 + a3));
                if (ex < bev) { bev = ex; bei = c; }
            }
            bi = bei;
        }
        s_idx[r] = bi;
        e_row = s_smu[r] + s_sc[r * 67 + bi];
    }
    __syncthreads();

    // =============== Phase 4: commitment, counts, z output =================
    const int flag_u8 = g_mask_u8;
    int validrow = 0;
    if (t < ROWS) {
        int rg = blk * ROWS + t;
        validrow = flag_u8 ? (((const unsigned char*)mask)[rg] == 0)
                           : (((const int*)mask)[rg] == 0);
        if (validrow) atomicAdd(&s_counts[s_idx[t]], 1);
    }
    float v = (t < ROWS && validrow) ? e_row : 0.f;
    #pragma unroll
    for (int o = 16; o > 0; o >>= 1) v += __shfl_down_sync(0xffffffffu, v, o);
    if ((t & 31) == 0) s_red[t >> 5] = v;
    __syncthreads();
    if (t == 0) {
        float tot = 0.f;
        for (int ww = 0; ww < 12; ww++) tot += s_red[ww];
        atomicAdd(&g_csum, tot);
    }
    if (t < KC_ && s_counts[t]) atomicAdd(&g_counts[t], s_counts[t]);

    // z = codebook[idx], vectorized
    float4* out4 = (float4*)(out + (size_t)blk * (ROWS * ZD));
    const float4* cb4 = (const float4*)cb;
    for (int i = t; i < ROWS * ZD / 4; i += THR) {
        int r = i >> 5, z4 = i & 31;
        out4[i] = cb4[s_idx[r] * 32 + z4];
    }
}

// ------------------------------ finalize ------------------------------------
__global__ void final_kernel(float* __restrict__ out)
{
    if (threadIdx.x == 0) {
        int nvi = 0;
        for (int k = 0; k < KC_; k++) nvi += g_counts[k];
        float nv = fmaxf((float)nvi, 1.f);
        float H = 0.f;
        for (int k = 0; k < KC_; k++) {
            float p = (float)g_counts[k] / nv;
            H += p * logf(p + 1e-10f);
        }
        out[(long)BS * ZD]     = 0.25f * g_csum / (nv * (float)ZD);
        out[(long)BS * ZD + 1] = expf(-H);
    }
}

// ------------------------------- launcher -----------------------------------
extern "C" void kernel_launch(void* const* d_in, const int* in_sizes, int n_in,
                              void* d_out, int out_size)
{
    const float* pr      = (const float*)d_in[0];
    const void*  mask    = d_in[1];
    const float* conv_w  = (const float*)d_in[2];
    const float* conv_b  = (const float*)d_in[3];
    const float* fc_w    = (const float*)d_in[4];
    const float* fc_b    = (const float*)d_in[5];
    const float* mu_w    = (const float*)d_in[6];
    const float* mu_b    = (const float*)d_in[7];
    const float* cb      = (const float*)d_in[8];
    float* out = (float*)d_out;

    cudaFuncSetAttribute(main_kernel,
                         cudaFuncAttributeMaxDynamicSharedMemorySize, SMEM_BYTES);

    setup_kernel<<<2, 512>>>(fc_b, mu_w, mu_b, cb,
                             (const unsigned char*)mask, BS);
    wfuse_kernel<<<KPAD / 4, 128>>>(fc_w, mu_w, cb);
    main_kernel<<<NBLK, THR, SMEM_BYTES>>>(pr, mask, conv_w, conv_b, cb, out);
    final_kernel<<<1, 32>>>(out);
}

// round 15
// speedup vs baseline: 2.9139x; 1.1324x over previous
#include <cuda_runtime.h>
#include <cuda_fp16.h>
#include <math.h>
#include <stdint.h>

// ----------------------------------------------------------------------------
// FuncPitchEncoder R14: R12 architecture + last-block finalize (no final
// kernel), merged pre-kernel (setup|detect|wfuse), warp-parallel refinement.
// ----------------------------------------------------------------------------

#define BS      131072
#define LEN     128
#define NCH     10
#define CONVK   12
#define POOLN   29
#define FEATN   290
#define EMB     256
#define ZD      128
#define KC_     64
#define ROWS    64
#define NBLK    (BS / ROWS)          // 2048
#define THR     384

#define KPAD    320                  // 20 k16 tiles
#define NTILES  24                   // 192 cols / 8
#define FSTR    66                   // featT row stride

// smem float offsets
#define FEATT_F   (FEATN * FSTR)     // 19140
#define OFF_SCR   FEATT_F
#define SCR_F     8192               // prs 4224 | afrag 2048u32 + bbuf 6144u32 | s_sc 4288
#define OFF_MISC  (OFF_SCR + SCR_F)  // 27332
#define SMEM_F    (OFF_MISC + 532 + 194)
#define SMEM_BYTES (SMEM_F * 4)      // 112232 B -> 2 CTAs/SM

// ----------------------------- helpers --------------------------------------
#define MMA16816(d, a, b) \
    asm volatile("mma.sync.aligned.m16n8k16.row.col.f32.f16.f16.f32 " \
        "{%0,%1,%2,%3}, {%4,%5,%6,%7}, {%8,%9}, {%0,%1,%2,%3};" \
        : "+f"((d)[0]), "+f"((d)[1]), "+f"((d)[2]), "+f"((d)[3]) \
        : "r"((a)[0]), "r"((a)[1]), "r"((a)[2]), "r"((a)[3]), \
          "r"((b)[0]), "r"((b)[1]))

__device__ __forceinline__ void cpasync16(uint32_t sdst, const void* g) {
    asm volatile("cp.async.cg.shared.global [%0], [%1], 16;" :: "r"(sdst), "l"(g));
}
#define CPASYNC_COMMIT() asm volatile("cp.async.commit_group;")
#define CPASYNC_WAIT0()  asm volatile("cp.async.wait_group 0;")

__device__ __forceinline__ uint32_t smem_u32(const void* p) {
    uint32_t a;
    asm("{ .reg .u64 t; cvta.to.shared.u64 t, %1; cvt.u32.u64 %0, t; }"
        : "=r"(a) : "l"(p));
    return a;
}

// ----------------------------- device scratch -------------------------------
__device__ __align__(16) float g_W[KPAD * ZD];          // fp32 fused W [k][j]
__device__ __align__(16) float g_U[KC_ * KPAD];         // fp32 U[c][k]
// B' fp16 fragments: [kt 20][ntile 24][lane 32][reg 2] u32
__device__ __align__(16) uint32_t g_Bfrag[20 * NTILES * 32 * 2];
__device__ float g_bf[ZD];
__device__ float g_sq[KC_];
__device__ int   g_UmaxI;
__device__ float g_csum;
__device__ int   g_counts[KC_];
__device__ int   g_mask_u8;
__device__ unsigned int g_done;

// --------------- pre-kernel: wfuse (0..79) | setup (80) | detect (81) -------
__global__ void pre_kernel(const float* __restrict__ fc_w,
                           const float* __restrict__ mu_w,
                           const float* __restrict__ fc_b,
                           const float* __restrict__ mu_b,
                           const float* __restrict__ cb,
                           const unsigned char* __restrict__ m, int n)
{
    int t = threadIdx.x;                 // 128 threads
    int bid = blockIdx.x;

    if (bid == 80) {
        // ---- setup: g_bf, g_sq, zeroing ----
        if (t == 0) { g_csum = 0.f; g_UmaxI = 0; g_done = 0u; }
        if (t < KC_) g_counts[t] = 0;
        {
            float a = mu_b[t];
            for (int e = 0; e < EMB; e++) a = fmaf(mu_w[t * EMB + e], fc_b[e], a);
            g_bf[t] = a;
        }
        __syncthreads();
        if (t < KC_) {
            const float* cc = cb + t * ZD;
            float cn = 0.f, bc = 0.f;
            #pragma unroll 4
            for (int z = 0; z < ZD; z++) {
                float cv = cc[z];
                cn = fmaf(cv, cv, cn);
                bc = fmaf(g_bf[z], cv, bc);
            }
            g_sq[t] = cn - 2.f * bc;
        }
        return;
    }
    if (bid == 81) {
        // ---- mask dtype detection (uint4): int32 0/1 has zero high bytes ----
        __shared__ int sf;
        if (t == 0) sf = 0;
        __syncthreads();
        const uint4* m4 = (const uint4*)m;
        int nw = n >> 4;
        int f = 0;
        for (int i = t; i < nw; i += 128) {
            uint4 v = m4[i];
            f |= (((v.x | v.y | v.z | v.w) & 0xFFFFFF00u) != 0u);
        }
        if (__any_sync(0xffffffffu, f)) { if ((t & 31) == 0) atomicOr(&sf, 1); }
        __syncthreads();
        if (t == 0) g_mask_u8 = sf;
        return;
    }

    // ---- wfuse: W, W-frags, U = W@C^T, U-frags, Umax ----
    __shared__ float colw[EMB * 4];
    __shared__ float Wsm[4 * ZD];
    __shared__ float cbs[KC_ * ZD];
    int k0 = bid * 4;
    for (int i = t; i < EMB * 4; i += 128) {
        int e = i >> 2, kk = i & 3, k = k0 + kk;
        colw[i] = (k < FEATN) ? fc_w[e * FEATN + k] : 0.f;
    }
    for (int i = t; i < KC_ * ZD; i += 128) cbs[i] = cb[i];
    __syncthreads();
    float a[4] = {0.f, 0.f, 0.f, 0.f};
    const float* mr = mu_w + t * EMB;
    #pragma unroll 4
    for (int e = 0; e < EMB; e++) {
        float mm = mr[e];
        a[0] = fmaf(mm, colw[e * 4 + 0], a[0]);
        a[1] = fmaf(mm, colw[e * 4 + 1], a[1]);
        a[2] = fmaf(mm, colw[e * 4 + 2], a[2]);
        a[3] = fmaf(mm, colw[e * 4 + 3], a[3]);
    }
    unsigned short* B16 = (unsigned short*)g_Bfrag;
    #pragma unroll
    for (int kk = 0; kk < 4; kk++) {
        int k = k0 + kk;                 // 0..319
        g_W[k * ZD + t] = a[kk];
        Wsm[kk * ZD + t] = a[kk];
        int gkt = k >> 4, klt = k & 15;
        int nt = t >> 3;
        int tB = ((t & 7) << 2) + ((klt & 7) >> 1);
        int regb = klt >> 3, half = klt & 1;
        B16[((((gkt * NTILES + nt) * 32 + tB) * 2 + regb) << 1) + half] =
            __half_as_ushort(__float2half_rn(a[kk]));
    }
    __syncthreads();
    float localmax = 0.f;
    #pragma unroll
    for (int pp = 0; pp < 2; pp++) {
        int idx = t + pp * 128;          // 0..255
        int c  = idx & 63;
        int kk = idx >> 6;
        int k  = k0 + kk;
        const float* wr = Wsm + kk * ZD;
        const float* cc = cbs + c * ZD;
        float a0 = 0.f, a1 = 0.f, a2 = 0.f, a3 = 0.f;
        #pragma unroll 8
        for (int z = 0; z < ZD; z += 4) {
            a0 = fmaf(wr[z + 0], cc[z + 0], a0);
            a1 = fmaf(wr[z + 1], cc[z + 1], a1);
            a2 = fmaf(wr[z + 2], cc[z + 2], a2);
            a3 = fmaf(wr[z + 3], cc[z + 3], a3);
        }
        float acc = (a0 + a1) + (a2 + a3);
        g_U[c * KPAD + k] = acc;
        localmax = fmaxf(localmax, fabsf(acc));
        int gkt = k >> 4, klt = k & 15;
        int nt = 16 + (c >> 3);
        int tB = ((c & 7) << 2) + ((klt & 7) >> 1);
        int regb = klt >> 3, half = klt & 1;
        B16[((((gkt * NTILES + nt) * 32 + tB) * 2 + regb) << 1) + half] =
            __half_as_ushort(__float2half_rn(acc));
    }
    #pragma unroll
    for (int o = 16; o > 0; o >>= 1)
        localmax = fmaxf(localmax, __shfl_xor_sync(0xffffffffu, localmax, o));
    if ((t & 31) == 0) atomicMax(&g_UmaxI, __float_as_int(localmax));
}

// --------------------------- conv worker (scalar) ----------------------------
__device__ __noinline__ void conv_item(const float* __restrict__ prs,
                                       float* __restrict__ featT,
                                       float* __restrict__ s_sabs,
                                       const float* __restrict__ s_convw,
                                       const float* __restrict__ s_convb,
                                       int item, int rowbase)
{
    int rl = item / NCH;
    int ch = item - rl * NCH;
    int rloc = rowbase + rl;
    float wr[CONVK];
    #pragma unroll
    for (int i = 0; i < CONVK; i++) wr[i] = s_convw[ch * CONVK + i];
    float bb = s_convb[ch];
    const float* prow = &prs[rl * 132];
    float* fp = &featT[ch * POOLN * FSTR + rloc];
    float x[15];
    #pragma unroll
    for (int i = 0; i < 15; i++) x[i] = prow[i];
    float ssum = 0.f;
    #pragma unroll
    for (int p = 0; p < POOLN; p++) {
        float m = 0.f;                   // relu >= 0
        #pragma unroll
        for (int j = 0; j < 4; j++) {
            float acc = bb;
            #pragma unroll
            for (int tt = 0; tt < CONVK; tt++)
                acc = fmaf(x[j + tt], wr[tt], acc);
            m = fmaxf(m, acc);
        }
        fp[p * FSTR] = m;
        ssum += m;
        if (p < POOLN - 1) {
            #pragma unroll
            for (int i = 0; i < 11; i++) x[i] = x[i + 4];
            #pragma unroll
            for (int i = 0; i < 4; i++) x[11 + i] = prow[4 * p + 15 + i];
        }
    }
    atomicAdd(&s_sabs[rloc], ssum);
}

// ------------------------------ main kernel ---------------------------------
__global__ __launch_bounds__(THR, 2)
void main_kernel(const float* __restrict__ pr,
                 const void*  __restrict__ mask,
                 const float* __restrict__ conv_w,
                 const float* __restrict__ conv_b,
                 const float* __restrict__ cb,
                 float* __restrict__ out)
{
    extern __shared__ float sm[];
    float* featT    = sm;                       // [290][66] — live to the end
    float* scr      = sm + OFF_SCR;             // prs | afrag+bbuf | s_sc
    float* s_convw  = sm + OFF_MISC;            // 120
    float* s_convb  = s_convw + 120;            // 12
    float* s_bf     = s_convb + 12;             // 128
    float* s_sq     = s_bf + 128;               // 64
    float* s_red    = s_sq + 64;                // 16
    float* s_smu    = s_red + 16;               // 64
    float* s_sabs   = s_smu + 64;               // 64
    float* s_thr    = s_sabs + 64;              // 64
    int*   s_idx    = (int*)(s_thr + 64);       // 64
    int*   s_counts = s_idx + 64;               // 64
    int*   s_q      = s_counts + 64;            // 64
    int*   s_qn     = s_q + 64;                 // 1

    const int t    = threadIdx.x;
    const int blk  = blockIdx.x;
    const int lane = t & 31;
    const int w    = t >> 5;                    // 0..11
    const int mi   = w / 6;                     // 0..1
    const int ni   = w % 6;                     // 0..5

    // ---- misc loads / zeroing ----
    for (int i = t; i < 120; i += THR) s_convw[i] = conv_w[i];
    if (t < NCH)  s_convb[t] = conv_b[t];
    if (t < ZD)   s_bf[t] = g_bf[t];
    if (t < ROWS) { s_smu[t] = 0.f; s_sabs[t] = 0.f; }
    if (t < KC_) { s_sq[t] = g_sq[t]; s_counts[t] = 0; }
    if (t == 0) s_qn[0] = 0;

    // =============== Phase 1: conv + relu + maxpool -> featT ===============
    float* prs = scr;                           // [32][132]
    for (int sub = 0; sub < 2; sub++) {
        int row0 = blk * ROWS + sub * 32;
        __syncthreads();
        const float4* src = (const float4*)(pr + (size_t)row0 * LEN);
        for (int i = t; i < 32 * 32; i += THR) {
            int rr = i >> 5, c4 = i & 31;
            *(float4*)&prs[rr * 132 + c4 * 4] = src[i];
        }
        __syncthreads();
        if (t < 320) conv_item(prs, featT, s_sabs, s_convw, s_convb, t, sub * 32);
    }
    __syncthreads();                            // featT complete, prs dead

    // =============== Phase 2: [feat] x [W|U] fp16 HMMA =====================
    uint32_t* afrag = (uint32_t*)scr;               // 2048 u32 (8KB)
    uint32_t* bbuf  = (uint32_t*)(scr + 2048);      // 6144 u32 (24KB)
    const uint32_t bbuf_sa = smem_u32(sm) + (OFF_SCR + 2048) * 4;

    float d[2][4][4];
    #pragma unroll
    for (int i = 0; i < 2; i++)
        #pragma unroll
        for (int j = 0; j < 4; j++)
            #pragma unroll
            for (int q = 0; q < 4; q++) d[i][j][q] = 0.f;

    for (int c = 0; c < 5; c++) {
        const char* bsrc = (const char*)g_Bfrag + (size_t)c * 24576;
        #pragma unroll
        for (int u = 0; u < 4; u++) {
            int i = t + u * THR;                // 0..1535
            cpasync16(bbuf_sa + i * 16, bsrc + i * 16);
        }
        CPASYNC_COMMIT();
        for (int i = t; i < 2048; i += THR) {
            int r   = i & 63;
            int kle = (i >> 6) * 2;
            int k = c * 64 + kle;
            float v0 = (k     < FEATN) ? featT[k * FSTR + r]       : 0.f;
            float v1 = (k + 1 < FEATN) ? featT[(k + 1) * FSTR + r] : 0.f;
            __half2 hh = __floats2half2_rn(v0, v1);
            int ktl = kle >> 4, klt = kle & 15;
            int reg = ((r & 15) >> 3) + ((klt >> 3) << 1);
            int tA  = ((r & 7) << 2) + ((klt & 7) >> 1);
            int mt  = r >> 4;
            afrag[((ktl * 4 + mt) << 7) + (tA << 2) + reg] = *(uint32_t*)&hh;
        }
        CPASYNC_WAIT0();
        __syncthreads();

        #pragma unroll
        for (int kt = 0; kt < 4; kt++) {
            uint32_t a[2][4];
            #pragma unroll
            for (int s2 = 0; s2 < 2; s2++) {
                uint4 aa = *(const uint4*)&afrag[((kt * 4 + mi * 2 + s2) << 7) + (lane << 2)];
                a[s2][0] = aa.x; a[s2][1] = aa.y; a[s2][2] = aa.z; a[s2][3] = aa.w;
            }
            uint32_t b[4][2];
            #pragma unroll
            for (int q = 0; q < 4; q++) {
                uint2 bb = *(const uint2*)&bbuf[((kt * NTILES + ni * 4 + q) * 32 + lane) * 2];
                b[q][0] = bb.x; b[q][1] = bb.y;
            }
            #pragma unroll
            for (int s2 = 0; s2 < 2; s2++)
                #pragma unroll
                for (int q = 0; q < 4; q++)
                    MMA16816(d[s2][q], a[s2], b[q]);
        }
        __syncthreads();
    }

    // =============== Epilogue: smu partials + approx scores ================
    float* s_sc = scr;                          // [64][67]
    {
        #pragma unroll
        for (int s2 = 0; s2 < 2; s2++)
            #pragma unroll
            for (int rh = 0; rh < 2; rh++) {
                int row = mi * 32 + (lane >> 2) + s2 * 16 + rh * 8;
                float smuP = 0.f;
                #pragma unroll
                for (int q = 0; q < 4; q++) {
                    int colb = (ni * 4 + q) * 8;
                    int col0 = colb + (lane & 3) * 2;
                    float v0 = d[s2][q][rh * 2 + 0];
                    float v1 = d[s2][q][rh * 2 + 1];
                    if (colb < 128) {
                        float m0 = v0 + s_bf[col0];
                        float m1 = v1 + s_bf[col0 + 1];
                        smuP = fmaf(m0, m0, smuP);
                        smuP = fmaf(m1, m1, smuP);
                    } else {
                        int cc = col0 - 128;
                        s_sc[row * 67 + cc]     = s_sq[cc]     - 2.f * v0;
                        s_sc[row * 67 + cc + 1] = s_sq[cc + 1] - 2.f * v1;
                    }
                }
                smuP += __shfl_xor_sync(0xffffffffu, smuP, 1);
                smuP += __shfl_xor_sync(0xffffffffu, smuP, 2);
                if ((lane & 3) == 0 && smuP != 0.f) atomicAdd(&s_smu[row], smuP);
            }
    }
    __syncthreads();

    // =============== Phase 3a: approx argmin + queue in-margin rows ========
    const float umax = __int_as_float(g_UmaxI);
    if (t < ROWS) {
        const int r = t;
        float marg = s_sabs[r] * umax * (1.0f / 256.0f);   // 2B bound
        float bv = 3.4e38f; int bi = 0;
        for (int c = 0; c < KC_; c++) {
            float s = s_sc[r * 67 + c];
            if (s < bv) { bv = s; bi = c; }
        }
        float thr = bv + marg;
        int ncand = 0;
        for (int c = 0; c < KC_; c++) ncand += (s_sc[r * 67 + c] <= thr);
        s_idx[r] = bi;
        if (ncand > 1) {
            int slot = atomicAdd(s_qn, 1);
            s_q[slot] = r;
            s_thr[r] = thr;
        }
    }
    __syncthreads();

    // =============== Phase 3b: warp-parallel exact refinement ==============
    {
        int qn = s_qn[0];
        for (int qi = w; qi < qn; qi += 12) {
            int r = s_q[qi];
            float thr = s_thr[r];
            float best = 3.4e38f; int bc = 0;
            for (int c = 0; c < KC_; c++) {
                if (s_sc[r * 67 + c] > thr) continue;
                const float* Uc = g_U + c * KPAD;
                float p = 0.f;
                for (int k = lane; k < FEATN; k += 32)
                    p = fmaf(featT[k * FSTR + r], __ldg(Uc + k), p);
                #pragma unroll
                for (int o = 16; o > 0; o >>= 1)
                    p += __shfl_xor_sync(0xffffffffu, p, o);
                float ex = s_sq[c] - 2.f * p;
                if (ex < best) { best = ex; bc = c; }
            }
            if (lane == 0) s_idx[r] = bc;
        }
    }
    __syncthreads();

    // =============== Phase 4: commitment, counts, z output =================
    const int flag_u8 = g_mask_u8;
    int validrow = 0;
    float e_row = 0.f;
    if (t < ROWS) {
        int rg = blk * ROWS + t;
        validrow = flag_u8 ? (((const unsigned char*)mask)[rg] == 0)
                           : (((const int*)mask)[rg] == 0);
        int myidx = s_idx[t];
        e_row = s_smu[t] + s_sc[t * 67 + myidx];
        if (validrow) atomicAdd(&s_counts[myidx], 1);
    }
    float v = (t < ROWS && validrow) ? e_row : 0.f;
    #pragma unroll
    for (int o = 16; o > 0; o >>= 1) v += __shfl_down_sync(0xffffffffu, v, o);
    if ((t & 31) == 0) s_red[t >> 5] = v;
    __syncthreads();
    if (t == 0) {
        float tot = 0.f;
        for (int ww = 0; ww < 12; ww++) tot += s_red[ww];
        atomicAdd(&g_csum, tot);
    }
    if (t < KC_ && s_counts[t]) atomicAdd(&g_counts[t], s_counts[t]);

    // z = codebook[idx], vectorized
    float4* out4 = (float4*)(out + (size_t)blk * (ROWS * ZD));
    const float4* cb4 = (const float4*)cb;
    for (int i = t; i < ROWS * ZD / 4; i += THR) {
        int r = i >> 5, z4 = i & 31;
        out4[i] = cb4[s_idx[r] * 32 + z4];
    }

    // =============== Last-block finalize (replaces final_kernel) ===========
    __syncthreads();
    if (t == 0) {
        __threadfence();
        if (atomicAdd(&g_done, 1u) == (unsigned)(NBLK - 1)) {
            int nvi = 0;
            for (int k = 0; k < KC_; k++) nvi += g_counts[k];
            float nv = fmaxf((float)nvi, 1.f);
            float H = 0.f;
            for (int k = 0; k < KC_; k++) {
                float p = (float)g_counts[k] / nv;
                H += p * logf(p + 1e-10f);
            }
            out[(long)BS * ZD]     = 0.25f * g_csum / (nv * (float)ZD);
            out[(long)BS * ZD + 1] = expf(-H);
        }
    }
}

// ------------------------------- launcher -----------------------------------
extern "C" void kernel_launch(void* const* d_in, const int* in_sizes, int n_in,
                              void* d_out, int out_size)
{
    const float* pr      = (const float*)d_in[0];
    const void*  mask    = d_in[1];
    const float* conv_w  = (const float*)d_in[2];
    const float* conv_b  = (const float*)d_in[3];
    const float* fc_w    = (const float*)d_in[4];
    const float* fc_b    = (const float*)d_in[5];
    const float* mu_w    = (const float*)d_in[6];
    const float* mu_b    = (const float*)d_in[7];
    const float* cb      = (const float*)d_in[8];
    float* out = (float*)d_out;

    cudaFuncSetAttribute(main_kernel,
                         cudaFuncAttributeMaxDynamicSharedMemorySize, SMEM_BYTES);

    pre_kernel<<<82, 128>>>(fc_w, mu_w, fc_b, mu_b, cb,
                            (const unsigned char*)mask, BS);
    main_kernel<<<NBLK, THR, SMEM_BYTES>>>(pr, mask, conv_w, conv_b, cb, out);
}